// round 6
// baseline (speedup 1.0000x reference)
#include <cuda_runtime.h>
#include <cuda_fp16.h>
#include <cuda_bf16.h>
#include <cstdint>

#define N_NODES 100000
#define N_EDGES 3200000
#define IN_CH   512
#define OUT_CH  64
#define SCAN_B  98          // ceil(N_NODES / 1024)

// ---- scratch: __device__ globals only ----
__device__ int g_is64;
__device__ __align__(16) int    g_rows  [N_EDGES];
__device__ __align__(16) int    g_cols  [N_EDGES];
__device__ __align__(16) int    g_cnt   [N_NODES];
__device__ __align__(16) int    g_rowptr[N_NODES + 1];
__device__ __align__(16) int    g_bsum  [SCAN_B];
__device__ __align__(16) int    g_bbase [SCAN_B];
__device__ __align__(16) float  g_dinv  [N_NODES];
__device__ __align__(16) int    g_ecol  [N_EDGES];
__device__ __align__(16) __half g_h0    [(size_t)N_NODES * OUT_CH]; // h0s = dinv*(xW)
__device__ __align__(16) __half g_h1    [(size_t)N_NODES * OUT_CH]; // h1s = dinv*h1
__device__ __align__(16) __nv_bfloat16 g_Wth[OUT_CH][IN_CH];
__device__ __align__(16) __nv_bfloat16 g_Wtl[OUT_CH][IN_CH];

// ---------------- dtype probe ----------------
__global__ void detect_kernel(const int* __restrict__ buf) {
    if (threadIdx.x == 0 && blockIdx.x == 0) {
        int any_odd_nonzero = 0;
        for (int i = 0; i < 2048; i++) {
            if (buf[2 * i + 1] != 0) { any_odd_nonzero = 1; break; }
        }
        g_is64 = any_odd_nonzero ? 0 : 1;
    }
}

__global__ void zero_cnt_kernel() {
    int i = blockIdx.x * blockDim.x + threadIdx.x;
    if (i < N_NODES) g_cnt[i] = 0;
}

// convert + histogram in one pass over edge_index
__global__ void convert_hist_kernel(const void* __restrict__ buf) {
    int e = blockIdx.x * blockDim.x + threadIdx.x;
    if (e >= N_EDGES) return;
    int r, c;
    if (g_is64) {
        const long long* p = (const long long*)buf;
        r = (int)p[e];
        c = (int)p[(size_t)N_EDGES + e];
    } else {
        const int* p = (const int*)buf;
        r = p[e];
        c = p[N_EDGES + e];
    }
    g_rows[e] = r;
    g_cols[e] = c;
    if ((unsigned)r >= N_NODES || (unsigned)c >= N_NODES) return;
    if (r != c) atomicAdd(&g_cnt[r], 1);
}

__global__ void dinv_kernel() {
    int i = blockIdx.x * blockDim.x + threadIdx.x;
    if (i < N_NODES) g_dinv[i] = rsqrtf((float)g_cnt[i] + 1.0f);
}

// ---------------- 3-phase scan: g_cnt -> g_rowptr ----------------
__global__ __launch_bounds__(1024) void scanA_kernel() {   // per-block sums
    __shared__ int wsum[32];
    int b = blockIdx.x, t = threadIdx.x;
    int i = b * 1024 + t;
    int v = (i < N_NODES) ? g_cnt[i] : 0;
    int lane = t & 31, wid = t >> 5;
    int s = v;
    #pragma unroll
    for (int off = 16; off > 0; off >>= 1) s += __shfl_xor_sync(~0u, s, off);
    if (lane == 0) wsum[wid] = s;
    __syncthreads();
    if (wid == 0) {
        int w = wsum[lane];
        #pragma unroll
        for (int off = 16; off > 0; off >>= 1) w += __shfl_xor_sync(~0u, w, off);
        if (lane == 0) g_bsum[b] = w;
    }
}

__global__ void scanB_kernel() {   // serial scan of SCAN_B partials (tiny)
    if (threadIdx.x == 0) {
        int acc = 0;
        for (int b = 0; b < SCAN_B; b++) { g_bbase[b] = acc; acc += g_bsum[b]; }
        g_rowptr[N_NODES] = acc;
    }
}

__global__ __launch_bounds__(1024) void scanC_kernel() {   // block-local exclusive scan
    __shared__ int wsum[32];
    int b = blockIdx.x, t = threadIdx.x;
    int i = b * 1024 + t;
    int v = (i < N_NODES) ? g_cnt[i] : 0;
    int lane = t & 31, wid = t >> 5;
    int incl = v;
    #pragma unroll
    for (int off = 1; off < 32; off <<= 1) {
        int n = __shfl_up_sync(~0u, incl, off);
        if (lane >= off) incl += n;
    }
    if (lane == 31) wsum[wid] = incl;
    __syncthreads();
    if (wid == 0) {
        int s = wsum[lane];
        #pragma unroll
        for (int off = 1; off < 32; off <<= 1) {
            int n = __shfl_up_sync(~0u, s, off);
            if (lane >= off) s += n;
        }
        wsum[lane] = s;
    }
    __syncthreads();
    if (i < N_NODES) {
        int excl = incl - v + (wid > 0 ? wsum[wid - 1] : 0) + g_bbase[b];
        g_rowptr[i] = excl;
    }
}

// scatter edges into CSR slots (atomicSub; consumes g_cnt)
__global__ void scatter_kernel() {
    int e = blockIdx.x * blockDim.x + threadIdx.x;
    if (e >= N_EDGES) return;
    int r = g_rows[e];
    int c = g_cols[e];
    if ((unsigned)r >= N_NODES || (unsigned)c >= N_NODES) return;
    if (r == c) return;
    int left = atomicSub(&g_cnt[r], 1);
    g_ecol[g_rowptr[r] + left - 1] = c;
}

// ---------------- W split/transpose ----------------
__global__ void wsplit_kernel(const float* __restrict__ W) {
    int t = blockIdx.x * blockDim.x + threadIdx.x;
    if (t >= IN_CH * OUT_CH) return;
    int n = t / IN_CH;
    int k = t % IN_CH;
    float v = W[(size_t)k * OUT_CH + n];
    __nv_bfloat16 hi = __float2bfloat16(v);
    __nv_bfloat16 lo = __float2bfloat16(v - __bfloat162float(hi));
    g_Wth[n][k] = hi;
    g_Wtl[n][k] = lo;
}

// ---------------- GEMM: g_h0 = fp16( dinv ⊙ (x @ W) ) ----------------
#define GBM 128
#define GBK 32
#define SAS 17

__device__ __forceinline__ uint32_t pack_bf16(__nv_bfloat16 a, __nv_bfloat16 b) {
    return (uint32_t)__bfloat16_as_ushort(a) | ((uint32_t)__bfloat16_as_ushort(b) << 16);
}

__device__ __forceinline__ void mma16816(float c[4], const uint32_t a[4],
                                         const uint32_t b[2]) {
    asm volatile(
        "mma.sync.aligned.m16n8k16.row.col.f32.bf16.bf16.f32 "
        "{%0,%1,%2,%3}, {%4,%5,%6,%7}, {%8,%9}, {%0,%1,%2,%3};"
        : "+f"(c[0]), "+f"(c[1]), "+f"(c[2]), "+f"(c[3])
        : "r"(a[0]), "r"(a[1]), "r"(a[2]), "r"(a[3]), "r"(b[0]), "r"(b[1]));
}

__global__ __launch_bounds__(256, 2) void gemm_mma_kernel(const float* __restrict__ x) {
    __shared__ uint32_t sAh[GBM][SAS];
    __shared__ uint32_t sAl[GBM][SAS];
    __shared__ uint32_t sBh[OUT_CH][SAS];
    __shared__ uint32_t sBl[OUT_CH][SAS];

    int tid  = threadIdx.x;
    int wid  = tid >> 5, lane = tid & 31;
    int wm   = wid & 3,  wn   = wid >> 2;
    int grp  = lane >> 2, t4  = lane & 3;
    int m0   = blockIdx.x * GBM;

    float c[2][4][4];
    #pragma unroll
    for (int i = 0; i < 2; i++)
        #pragma unroll
        for (int j = 0; j < 4; j++)
            #pragma unroll
            for (int k = 0; k < 4; k++) c[i][j][k] = 0.0f;

    for (int k0 = 0; k0 < IN_CH; k0 += GBK) {
        #pragma unroll
        for (int i = 0; i < 4; i++) {
            int idx = tid + i * 256;
            int row = idx >> 3;
            int f4  = idx & 7;
            float4 v = make_float4(0.f, 0.f, 0.f, 0.f);
            if (m0 + row < N_NODES)
                v = *(const float4*)(x + (size_t)(m0 + row) * IN_CH + k0 + f4 * 4);
            __nv_bfloat16 hx = __float2bfloat16(v.x);
            __nv_bfloat16 hy = __float2bfloat16(v.y);
            __nv_bfloat16 hz = __float2bfloat16(v.z);
            __nv_bfloat16 hw = __float2bfloat16(v.w);
            sAh[row][f4 * 2]     = pack_bf16(hx, hy);
            sAh[row][f4 * 2 + 1] = pack_bf16(hz, hw);
            __nv_bfloat16 lx = __float2bfloat16(v.x - __bfloat162float(hx));
            __nv_bfloat16 ly = __float2bfloat16(v.y - __bfloat162float(hy));
            __nv_bfloat16 lz = __float2bfloat16(v.z - __bfloat162float(hz));
            __nv_bfloat16 lw = __float2bfloat16(v.w - __bfloat162float(hw));
            sAl[row][f4 * 2]     = pack_bf16(lx, ly);
            sAl[row][f4 * 2 + 1] = pack_bf16(lz, lw);
        }
        #pragma unroll
        for (int i = 0; i < 4; i++) {
            int idx = tid + i * 256;
            int n  = idx >> 4;
            int kp = idx & 15;
            sBh[n][kp] = ((const uint32_t*)&g_Wth[n][k0])[kp];
            sBl[n][kp] = ((const uint32_t*)&g_Wtl[n][k0])[kp];
        }
        __syncthreads();

        #pragma unroll
        for (int kt = 0; kt < 2; kt++) {
            int kp0 = kt * 8;
            uint32_t ah[2][4], al[2][4];
            #pragma unroll
            for (int mt = 0; mt < 2; mt++) {
                int r = wm * 32 + mt * 16 + grp;
                ah[mt][0] = sAh[r][kp0 + t4];
                ah[mt][1] = sAh[r + 8][kp0 + t4];
                ah[mt][2] = sAh[r][kp0 + t4 + 4];
                ah[mt][3] = sAh[r + 8][kp0 + t4 + 4];
                al[mt][0] = sAl[r][kp0 + t4];
                al[mt][1] = sAl[r + 8][kp0 + t4];
                al[mt][2] = sAl[r][kp0 + t4 + 4];
                al[mt][3] = sAl[r + 8][kp0 + t4 + 4];
            }
            uint32_t bh[4][2], bl[4][2];
            #pragma unroll
            for (int nt = 0; nt < 4; nt++) {
                int n = wn * 32 + nt * 8 + grp;
                bh[nt][0] = sBh[n][kp0 + t4];
                bh[nt][1] = sBh[n][kp0 + t4 + 4];
                bl[nt][0] = sBl[n][kp0 + t4];
                bl[nt][1] = sBl[n][kp0 + t4 + 4];
            }
            #pragma unroll
            for (int mt = 0; mt < 2; mt++)
                #pragma unroll
                for (int nt = 0; nt < 4; nt++) {
                    mma16816(c[mt][nt], ah[mt], bh[nt]);
                    mma16816(c[mt][nt], ah[mt], bl[nt]);
                    mma16816(c[mt][nt], al[mt], bh[nt]);
                }
        }
        __syncthreads();
    }

    // epilogue: scale by dinv, store h0s as fp16
    #pragma unroll
    for (int mt = 0; mt < 2; mt++) {
        int r0 = m0 + wm * 32 + mt * 16 + grp;
        int r1 = r0 + 8;
        float d0 = (r0 < N_NODES) ? g_dinv[r0] : 0.0f;
        float d1 = (r1 < N_NODES) ? g_dinv[r1] : 0.0f;
        #pragma unroll
        for (int nt = 0; nt < 4; nt++) {
            int col = wn * 32 + nt * 8 + t4 * 2;
            if (r0 < N_NODES) {
                __half2 v = __floats2half2_rn(c[mt][nt][0] * d0, c[mt][nt][1] * d0);
                *(__half2*)(g_h0 + (size_t)r0 * OUT_CH + col) = v;
            }
            if (r1 < N_NODES) {
                __half2 v = __floats2half2_rn(c[mt][nt][2] * d1, c[mt][nt][3] * d1);
                *(__half2*)(g_h0 + (size_t)r1 * OUT_CH + col) = v;
            }
        }
    }
}

// ---------------- gather propagation (warp/node, fp16 rows, 8 lanes/edge) ---
// MODE 0: hin=g_h0, hout=g_h1 (fp16), scale=d^2
// MODE 1: hin=g_h1, hout=outp (fp32), scale=d
template <int MODE>
__global__ __launch_bounds__(256) void gather_kernel(float* __restrict__ outp) {
    int node = (int)((blockIdx.x * blockDim.x + threadIdx.x) >> 5);
    if (node >= N_NODES) return;
    int lane = threadIdx.x & 31;
    int sub  = lane & 7;             // 8-half chunk index (16B)
    int eoff = lane >> 3;            // 0..3: edge within group of 4

    const __half* __restrict__ hin = (MODE == 0) ? g_h0 : g_h1;

    int start = g_rowptr[node];
    int end   = g_rowptr[node + 1];

    float acc[8];
    #pragma unroll
    for (int i = 0; i < 8; i++) acc[i] = 0.0f;

    for (int e = start + eoff; e < end; e += 4) {
        int c = g_ecol[e];
        uint4 u = ((const uint4*)(hin + (size_t)c * OUT_CH))[sub];
        float2 f;
        f = __half22float2(*(__half2*)&u.x); acc[0] += f.x; acc[1] += f.y;
        f = __half22float2(*(__half2*)&u.y); acc[2] += f.x; acc[3] += f.y;
        f = __half22float2(*(__half2*)&u.z); acc[4] += f.x; acc[5] += f.y;
        f = __half22float2(*(__half2*)&u.w); acc[6] += f.x; acc[7] += f.y;
    }
    // combine lanes with the same sub (xor 8, xor 16)
    #pragma unroll
    for (int i = 0; i < 8; i++) {
        acc[i] += __shfl_xor_sync(0xFFFFFFFFu, acc[i], 8);
        acc[i] += __shfl_xor_sync(0xFFFFFFFFu, acc[i], 16);
    }

    if (lane < 8) {
        float d = g_dinv[node];
        float s = (MODE == 0) ? d * d : d;
        uint4 u = ((const uint4*)(hin + (size_t)node * OUT_CH))[sub];
        float2 f;
        f = __half22float2(*(__half2*)&u.x); acc[0] += f.x; acc[1] += f.y;
        f = __half22float2(*(__half2*)&u.y); acc[2] += f.x; acc[3] += f.y;
        f = __half22float2(*(__half2*)&u.z); acc[4] += f.x; acc[5] += f.y;
        f = __half22float2(*(__half2*)&u.w); acc[6] += f.x; acc[7] += f.y;
        #pragma unroll
        for (int i = 0; i < 8; i++) acc[i] *= s;

        if (MODE == 0) {
            __half2 o[4];
            #pragma unroll
            for (int j = 0; j < 4; j++)
                o[j] = __floats2half2_rn(acc[2 * j], acc[2 * j + 1]);
            ((uint4*)(g_h1 + (size_t)node * OUT_CH))[sub] = *(uint4*)o;
        } else {
            float4 v0 = make_float4(acc[0], acc[1], acc[2], acc[3]);
            float4 v1 = make_float4(acc[4], acc[5], acc[6], acc[7]);
            float* dst = outp + (size_t)node * OUT_CH + sub * 8;
            *(float4*)(dst)     = v0;
            *(float4*)(dst + 4) = v1;
        }
    }
}

extern "C" void kernel_launch(void* const* d_in, const int* in_sizes, int n_in,
                              void* d_out, int out_size) {
    const void*  edge_index = d_in[0];               // [2, N_EDGES] int32 or int64
    const float* x          = (const float*)d_in[1]; // [N_NODES, 512]
    const float* W          = (const float*)d_in[2]; // [512, 64]
    float*       out        = (float*)d_out;         // [N_NODES, 64]

    detect_kernel<<<1, 32>>>((const int*)edge_index);
    zero_cnt_kernel<<<(N_NODES + 255) / 256, 256>>>();
    convert_hist_kernel<<<(N_EDGES + 255) / 256, 256>>>(edge_index);

    scanA_kernel<<<SCAN_B, 1024>>>();
    scanB_kernel<<<1, 32>>>();
    scanC_kernel<<<SCAN_B, 1024>>>();
    dinv_kernel<<<(N_NODES + 255) / 256, 256>>>();
    scatter_kernel<<<(N_EDGES + 255) / 256, 256>>>();

    wsplit_kernel<<<(IN_CH * OUT_CH + 255) / 256, 256>>>(W);
    gemm_mma_kernel<<<(N_NODES + GBM - 1) / GBM, 256>>>(x);

    const int blocks = (N_NODES * 32 + 255) / 256;
    gather_kernel<0><<<blocks, 256>>>(nullptr);
    gather_kernel<1><<<blocks, 256>>>(out);
}

// round 7
// speedup vs baseline: 1.3958x; 1.3958x over previous
#include <cuda_runtime.h>
#include <cuda_bf16.h>
#include <cstdint>

#define N_NODES 100000
#define N_EDGES 3200000
#define IN_CH   512
#define OUT_CH  64
#define SCAN_B  98          // ceil(N_NODES / 1024)

// ---- scratch: __device__ globals only ----
__device__ int g_is64;
__device__ __align__(16) int   g_rows  [N_EDGES];
__device__ __align__(16) int   g_cols  [N_EDGES];
__device__ __align__(16) int   g_cnt   [N_NODES];
__device__ __align__(16) int   g_rowptr[N_NODES + 1];
__device__ __align__(16) int   g_bsum  [SCAN_B];
__device__ __align__(16) int   g_bbase [SCAN_B];
__device__ __align__(16) float g_dinv  [N_NODES];
__device__ __align__(16) int   g_ecol  [N_EDGES];
__device__ __align__(16) float g_h0    [(size_t)N_NODES * OUT_CH];  // h0s = dinv*(xW)
__device__ __align__(16) float g_h1    [(size_t)N_NODES * OUT_CH];  // h1s = dinv*h1
__device__ __align__(16) __nv_bfloat16 g_Wth[OUT_CH][IN_CH];
__device__ __align__(16) __nv_bfloat16 g_Wtl[OUT_CH][IN_CH];

// ---------------- dtype probe ----------------
__global__ void detect_kernel(const int* __restrict__ buf) {
    if (threadIdx.x == 0 && blockIdx.x == 0) {
        int any_odd_nonzero = 0;
        for (int i = 0; i < 2048; i++) {
            if (buf[2 * i + 1] != 0) { any_odd_nonzero = 1; break; }
        }
        g_is64 = any_odd_nonzero ? 0 : 1;
    }
}

__global__ void zero_cnt_kernel() {
    int i = blockIdx.x * blockDim.x + threadIdx.x;
    if (i < N_NODES) g_cnt[i] = 0;
}

// convert + histogram in one pass over edge_index
__global__ void convert_hist_kernel(const void* __restrict__ buf) {
    int e = blockIdx.x * blockDim.x + threadIdx.x;
    if (e >= N_EDGES) return;
    int r, c;
    if (g_is64) {
        const long long* p = (const long long*)buf;
        r = (int)p[e];
        c = (int)p[(size_t)N_EDGES + e];
    } else {
        const int* p = (const int*)buf;
        r = p[e];
        c = p[N_EDGES + e];
    }
    g_rows[e] = r;
    g_cols[e] = c;
    if ((unsigned)r >= N_NODES || (unsigned)c >= N_NODES) return;
    if (r != c) atomicAdd(&g_cnt[r], 1);
}

__global__ void dinv_kernel() {
    int i = blockIdx.x * blockDim.x + threadIdx.x;
    if (i < N_NODES) g_dinv[i] = rsqrtf((float)g_cnt[i] + 1.0f);
}

// ---------------- 3-phase scan: g_cnt -> g_rowptr ----------------
__global__ __launch_bounds__(1024) void scanA_kernel() {   // per-block sums
    __shared__ int wsum[32];
    int b = blockIdx.x, t = threadIdx.x;
    int i = b * 1024 + t;
    int v = (i < N_NODES) ? g_cnt[i] : 0;
    int lane = t & 31, wid = t >> 5;
    int s = v;
    #pragma unroll
    for (int off = 16; off > 0; off >>= 1) s += __shfl_xor_sync(~0u, s, off);
    if (lane == 0) wsum[wid] = s;
    __syncthreads();
    if (wid == 0) {
        int w = wsum[lane];
        #pragma unroll
        for (int off = 16; off > 0; off >>= 1) w += __shfl_xor_sync(~0u, w, off);
        if (lane == 0) g_bsum[b] = w;
    }
}

__global__ void scanB_kernel() {   // serial scan of SCAN_B partials (tiny)
    if (threadIdx.x == 0) {
        int acc = 0;
        for (int b = 0; b < SCAN_B; b++) { g_bbase[b] = acc; acc += g_bsum[b]; }
        g_rowptr[N_NODES] = acc;
    }
}

__global__ __launch_bounds__(1024) void scanC_kernel() {   // block-local exclusive scan
    __shared__ int wsum[32];
    int b = blockIdx.x, t = threadIdx.x;
    int i = b * 1024 + t;
    int v = (i < N_NODES) ? g_cnt[i] : 0;
    int lane = t & 31, wid = t >> 5;
    int incl = v;
    #pragma unroll
    for (int off = 1; off < 32; off <<= 1) {
        int n = __shfl_up_sync(~0u, incl, off);
        if (lane >= off) incl += n;
    }
    if (lane == 31) wsum[wid] = incl;
    __syncthreads();
    if (wid == 0) {
        int s = wsum[lane];
        #pragma unroll
        for (int off = 1; off < 32; off <<= 1) {
            int n = __shfl_up_sync(~0u, s, off);
            if (lane >= off) s += n;
        }
        wsum[lane] = s;
    }
    __syncthreads();
    if (i < N_NODES) {
        int excl = incl - v + (wid > 0 ? wsum[wid - 1] : 0) + g_bbase[b];
        g_rowptr[i] = excl;
    }
}

// scatter edges into CSR slots (atomicSub; consumes g_cnt)
__global__ void scatter_kernel() {
    int e = blockIdx.x * blockDim.x + threadIdx.x;
    if (e >= N_EDGES) return;
    int r = g_rows[e];
    int c = g_cols[e];
    if ((unsigned)r >= N_NODES || (unsigned)c >= N_NODES) return;
    if (r == c) return;
    int left = atomicSub(&g_cnt[r], 1);
    g_ecol[g_rowptr[r] + left - 1] = c;
}

// ---------------- W split/transpose ----------------
__global__ void wsplit_kernel(const float* __restrict__ W) {
    int t = blockIdx.x * blockDim.x + threadIdx.x;
    if (t >= IN_CH * OUT_CH) return;
    int n = t / IN_CH;
    int k = t % IN_CH;
    float v = W[(size_t)k * OUT_CH + n];
    __nv_bfloat16 hi = __float2bfloat16(v);
    __nv_bfloat16 lo = __float2bfloat16(v - __bfloat162float(hi));
    g_Wth[n][k] = hi;
    g_Wtl[n][k] = lo;
}

// ---------------- GEMM: g_h0 = dinv ⊙ (x @ W) via bf16-split mma.sync ------
#define GBM 128
#define GBK 32
#define SAS 17

__device__ __forceinline__ uint32_t pack_bf16(__nv_bfloat16 a, __nv_bfloat16 b) {
    return (uint32_t)__bfloat16_as_ushort(a) | ((uint32_t)__bfloat16_as_ushort(b) << 16);
}

__device__ __forceinline__ void mma16816(float c[4], const uint32_t a[4],
                                         const uint32_t b[2]) {
    asm volatile(
        "mma.sync.aligned.m16n8k16.row.col.f32.bf16.bf16.f32 "
        "{%0,%1,%2,%3}, {%4,%5,%6,%7}, {%8,%9}, {%0,%1,%2,%3};"
        : "+f"(c[0]), "+f"(c[1]), "+f"(c[2]), "+f"(c[3])
        : "r"(a[0]), "r"(a[1]), "r"(a[2]), "r"(a[3]), "r"(b[0]), "r"(b[1]));
}

__global__ __launch_bounds__(256, 2) void gemm_mma_kernel(const float* __restrict__ x) {
    __shared__ uint32_t sAh[GBM][SAS];
    __shared__ uint32_t sAl[GBM][SAS];
    __shared__ uint32_t sBh[OUT_CH][SAS];
    __shared__ uint32_t sBl[OUT_CH][SAS];

    int tid  = threadIdx.x;
    int wid  = tid >> 5, lane = tid & 31;
    int wm   = wid & 3,  wn   = wid >> 2;
    int grp  = lane >> 2, t4  = lane & 3;
    int m0   = blockIdx.x * GBM;

    float c[2][4][4];
    #pragma unroll
    for (int i = 0; i < 2; i++)
        #pragma unroll
        for (int j = 0; j < 4; j++)
            #pragma unroll
            for (int k = 0; k < 4; k++) c[i][j][k] = 0.0f;

    for (int k0 = 0; k0 < IN_CH; k0 += GBK) {
        #pragma unroll
        for (int i = 0; i < 4; i++) {
            int idx = tid + i * 256;
            int row = idx >> 3;
            int f4  = idx & 7;
            float4 v = make_float4(0.f, 0.f, 0.f, 0.f);
            if (m0 + row < N_NODES)
                v = *(const float4*)(x + (size_t)(m0 + row) * IN_CH + k0 + f4 * 4);
            __nv_bfloat16 hx = __float2bfloat16(v.x);
            __nv_bfloat16 hy = __float2bfloat16(v.y);
            __nv_bfloat16 hz = __float2bfloat16(v.z);
            __nv_bfloat16 hw = __float2bfloat16(v.w);
            sAh[row][f4 * 2]     = pack_bf16(hx, hy);
            sAh[row][f4 * 2 + 1] = pack_bf16(hz, hw);
            __nv_bfloat16 lx = __float2bfloat16(v.x - __bfloat162float(hx));
            __nv_bfloat16 ly = __float2bfloat16(v.y - __bfloat162float(hy));
            __nv_bfloat16 lz = __float2bfloat16(v.z - __bfloat162float(hz));
            __nv_bfloat16 lw = __float2bfloat16(v.w - __bfloat162float(hw));
            sAl[row][f4 * 2]     = pack_bf16(lx, ly);
            sAl[row][f4 * 2 + 1] = pack_bf16(lz, lw);
        }
        #pragma unroll
        for (int i = 0; i < 4; i++) {
            int idx = tid + i * 256;
            int n  = idx >> 4;
            int kp = idx & 15;
            sBh[n][kp] = ((const uint32_t*)&g_Wth[n][k0])[kp];
            sBl[n][kp] = ((const uint32_t*)&g_Wtl[n][k0])[kp];
        }
        __syncthreads();

        #pragma unroll
        for (int kt = 0; kt < 2; kt++) {
            int kp0 = kt * 8;
            uint32_t ah[2][4], al[2][4];
            #pragma unroll
            for (int mt = 0; mt < 2; mt++) {
                int r = wm * 32 + mt * 16 + grp;
                ah[mt][0] = sAh[r][kp0 + t4];
                ah[mt][1] = sAh[r + 8][kp0 + t4];
                ah[mt][2] = sAh[r][kp0 + t4 + 4];
                ah[mt][3] = sAh[r + 8][kp0 + t4 + 4];
                al[mt][0] = sAl[r][kp0 + t4];
                al[mt][1] = sAl[r + 8][kp0 + t4];
                al[mt][2] = sAl[r][kp0 + t4 + 4];
                al[mt][3] = sAl[r + 8][kp0 + t4 + 4];
            }
            uint32_t bh[4][2], bl[4][2];
            #pragma unroll
            for (int nt = 0; nt < 4; nt++) {
                int n = wn * 32 + nt * 8 + grp;
                bh[nt][0] = sBh[n][kp0 + t4];
                bh[nt][1] = sBh[n][kp0 + t4 + 4];
                bl[nt][0] = sBl[n][kp0 + t4];
                bl[nt][1] = sBl[n][kp0 + t4 + 4];
            }
            #pragma unroll
            for (int mt = 0; mt < 2; mt++)
                #pragma unroll
                for (int nt = 0; nt < 4; nt++) {
                    mma16816(c[mt][nt], ah[mt], bh[nt]);
                    mma16816(c[mt][nt], ah[mt], bl[nt]);
                    mma16816(c[mt][nt], al[mt], bh[nt]);
                }
        }
        __syncthreads();
    }

    // epilogue: scale by dinv, store h0s (fp32)
    #pragma unroll
    for (int mt = 0; mt < 2; mt++) {
        int r0 = m0 + wm * 32 + mt * 16 + grp;
        int r1 = r0 + 8;
        float d0 = (r0 < N_NODES) ? g_dinv[r0] : 0.0f;
        float d1 = (r1 < N_NODES) ? g_dinv[r1] : 0.0f;
        #pragma unroll
        for (int nt = 0; nt < 4; nt++) {
            int col = wn * 32 + nt * 8 + t4 * 2;
            if (r0 < N_NODES) {
                float2 v = make_float2(c[mt][nt][0] * d0, c[mt][nt][1] * d0);
                *(float2*)(g_h0 + (size_t)r0 * OUT_CH + col) = v;
            }
            if (r1 < N_NODES) {
                float2 v = make_float2(c[mt][nt][2] * d1, c[mt][nt][3] * d1);
                *(float2*)(g_h0 + (size_t)r1 * OUT_CH + col) = v;
            }
        }
    }
}

// ---------------- gather-based propagation (one warp per node, fp32) --------
// out[r] = scale * (sum_{c in N(r)} hin[c] + hin[r])
// MODE 0: hin=g_h0, hout=g_h1, scale=d^2
// MODE 1: hin=g_h1, hout=outp, scale=d
template <int MODE>
__global__ __launch_bounds__(256) void gather_kernel(float* __restrict__ outp) {
    int node = (int)((blockIdx.x * blockDim.x + threadIdx.x) >> 5);
    if (node >= N_NODES) return;
    int lane = threadIdx.x & 31;

    const float* __restrict__ hin  = (MODE == 0) ? g_h0 : g_h1;
    float*       __restrict__ hout = (MODE == 0) ? g_h1 : outp;

    int start = g_rowptr[node];
    int end   = g_rowptr[node + 1];
    int c4 = (lane & 15) << 2;          // float4 column offset: 0..60

    float4 acc = make_float4(0.f, 0.f, 0.f, 0.f);
    #pragma unroll 2
    for (int e = start + (lane >> 4); e < end; e += 2) {
        int c = g_ecol[e];
        float4 v = *(const float4*)(hin + (size_t)c * OUT_CH + c4);
        acc.x += v.x; acc.y += v.y; acc.z += v.z; acc.w += v.w;
    }
    acc.x += __shfl_xor_sync(0xFFFFFFFFu, acc.x, 16);
    acc.y += __shfl_xor_sync(0xFFFFFFFFu, acc.y, 16);
    acc.z += __shfl_xor_sync(0xFFFFFFFFu, acc.z, 16);
    acc.w += __shfl_xor_sync(0xFFFFFFFFu, acc.w, 16);

    if (lane < 16) {
        float d = g_dinv[node];
        float s = (MODE == 0) ? d * d : d;
        float4 sv = *(const float4*)(hin + (size_t)node * OUT_CH + c4);
        acc.x = s * (acc.x + sv.x);
        acc.y = s * (acc.y + sv.y);
        acc.z = s * (acc.z + sv.z);
        acc.w = s * (acc.w + sv.w);
        *(float4*)(hout + (size_t)node * OUT_CH + c4) = acc;
    }
}

extern "C" void kernel_launch(void* const* d_in, const int* in_sizes, int n_in,
                              void* d_out, int out_size) {
    const void*  edge_index = d_in[0];               // [2, N_EDGES] int32 or int64
    const float* x          = (const float*)d_in[1]; // [N_NODES, 512]
    const float* W          = (const float*)d_in[2]; // [512, 64]
    float*       out        = (float*)d_out;         // [N_NODES, 64]

    detect_kernel<<<1, 32>>>((const int*)edge_index);
    zero_cnt_kernel<<<(N_NODES + 255) / 256, 256>>>();
    convert_hist_kernel<<<(N_EDGES + 255) / 256, 256>>>(edge_index);

    scanA_kernel<<<SCAN_B, 1024>>>();
    scanB_kernel<<<1, 32>>>();
    scanC_kernel<<<SCAN_B, 1024>>>();
    dinv_kernel<<<(N_NODES + 255) / 256, 256>>>();
    scatter_kernel<<<(N_EDGES + 255) / 256, 256>>>();

    wsplit_kernel<<<(IN_CH * OUT_CH + 255) / 256, 256>>>(W);
    gemm_mma_kernel<<<(N_NODES + GBM - 1) / GBM, 256>>>(x);

    const int blocks = (N_NODES * 32 + 255) / 256;
    gather_kernel<0><<<blocks, 256>>>(nullptr);
    gather_kernel<1><<<blocks, 256>>>(out);
}

// round 8
// speedup vs baseline: 1.4522x; 1.0404x over previous
#include <cuda_runtime.h>
#include <cuda_bf16.h>
#include <cstdint>

#define N_NODES 100000
#define N_EDGES 3200000
#define IN_CH   512
#define OUT_CH  64
#define SCAN_B  98          // ceil(N_NODES / 1024)

// ---- scratch: __device__ globals only ----
__device__ int g_is64;
__device__ __align__(16) int   g_cnt   [N_NODES];
__device__ __align__(16) int   g_rowptr[N_NODES + 1];
__device__ __align__(16) int   g_bsum  [SCAN_B];
__device__ __align__(16) int   g_bbase [SCAN_B];
__device__ __align__(16) float g_dinv  [N_NODES];
__device__ __align__(16) int   g_ecol  [N_EDGES];
__device__ __align__(16) float g_h0    [(size_t)N_NODES * OUT_CH];  // h0s = dinv*(xW)
__device__ __align__(16) float g_h1    [(size_t)N_NODES * OUT_CH];  // h1s = dinv*h1
__device__ __align__(16) __nv_bfloat16 g_Wth[OUT_CH][IN_CH];
__device__ __align__(16) __nv_bfloat16 g_Wtl[OUT_CH][IN_CH];

// ---------------- zero counts + dtype probe (one launch) ----------------
__global__ void zero_detect_kernel(const int* __restrict__ buf) {
    int i = blockIdx.x * blockDim.x + threadIdx.x;
    if (i < N_NODES) g_cnt[i] = 0;
    if (blockIdx.x == 0 && threadIdx.x == 0) {
        int any_odd_nonzero = 0;
        for (int j = 0; j < 2048; j++) {
            if (buf[2 * j + 1] != 0) { any_odd_nonzero = 1; break; }
        }
        g_is64 = any_odd_nonzero ? 0 : 1;
    }
}

// edge fetch helper: reads (r, c) for edge e under either dtype
__device__ __forceinline__ void load_edge(const void* buf, int e, int& r, int& c) {
    if (g_is64) {
        const long long* p = (const long long*)buf;
        r = (int)p[e];
        c = (int)p[(size_t)N_EDGES + e];
    } else {
        const int* p = (const int*)buf;
        r = p[e];
        c = p[N_EDGES + e];
    }
}

__global__ void hist_kernel(const void* __restrict__ buf) {
    int e = blockIdx.x * blockDim.x + threadIdx.x;
    if (e >= N_EDGES) return;
    int r, c;
    load_edge(buf, e, r, c);
    if ((unsigned)r >= N_NODES || (unsigned)c >= N_NODES) return;
    if (r != c) atomicAdd(&g_cnt[r], 1);
}

// ---------------- 3-phase scan: g_cnt -> g_rowptr (+ dinv in phase C) -------
__global__ __launch_bounds__(1024) void scanA_kernel() {
    __shared__ int wsum[32];
    int b = blockIdx.x, t = threadIdx.x;
    int i = b * 1024 + t;
    int v = (i < N_NODES) ? g_cnt[i] : 0;
    int lane = t & 31, wid = t >> 5;
    int s = v;
    #pragma unroll
    for (int off = 16; off > 0; off >>= 1) s += __shfl_xor_sync(~0u, s, off);
    if (lane == 0) wsum[wid] = s;
    __syncthreads();
    if (wid == 0) {
        int w = wsum[lane];
        #pragma unroll
        for (int off = 16; off > 0; off >>= 1) w += __shfl_xor_sync(~0u, w, off);
        if (lane == 0) g_bsum[b] = w;
    }
}

__global__ void scanB_kernel() {
    if (threadIdx.x == 0) {
        int acc = 0;
        for (int b = 0; b < SCAN_B; b++) { g_bbase[b] = acc; acc += g_bsum[b]; }
        g_rowptr[N_NODES] = acc;
    }
}

__global__ __launch_bounds__(1024) void scanC_kernel() {
    __shared__ int wsum[32];
    int b = blockIdx.x, t = threadIdx.x;
    int i = b * 1024 + t;
    int v = (i < N_NODES) ? g_cnt[i] : 0;
    int lane = t & 31, wid = t >> 5;
    int incl = v;
    #pragma unroll
    for (int off = 1; off < 32; off <<= 1) {
        int n = __shfl_up_sync(~0u, incl, off);
        if (lane >= off) incl += n;
    }
    if (lane == 31) wsum[wid] = incl;
    __syncthreads();
    if (wid == 0) {
        int s = wsum[lane];
        #pragma unroll
        for (int off = 1; off < 32; off <<= 1) {
            int n = __shfl_up_sync(~0u, s, off);
            if (lane >= off) s += n;
        }
        wsum[lane] = s;
    }
    __syncthreads();
    if (i < N_NODES) {
        int excl = incl - v + (wid > 0 ? wsum[wid - 1] : 0) + g_bbase[b];
        g_rowptr[i] = excl;
        g_dinv[i]   = rsqrtf((float)v + 1.0f);   // fused dinv
    }
}

// scatter edges into CSR slots (atomicSub; consumes g_cnt)
__global__ void scatter_kernel(const void* __restrict__ buf) {
    int e = blockIdx.x * blockDim.x + threadIdx.x;
    if (e >= N_EDGES) return;
    int r, c;
    load_edge(buf, e, r, c);
    if ((unsigned)r >= N_NODES || (unsigned)c >= N_NODES) return;
    if (r == c) return;
    int left = atomicSub(&g_cnt[r], 1);
    g_ecol[g_rowptr[r] + left - 1] = c;
}

// ---------------- W split/transpose ----------------
__global__ void wsplit_kernel(const float* __restrict__ W) {
    int t = blockIdx.x * blockDim.x + threadIdx.x;
    if (t >= IN_CH * OUT_CH) return;
    int n = t / IN_CH;
    int k = t % IN_CH;
    float v = W[(size_t)k * OUT_CH + n];
    __nv_bfloat16 hi = __float2bfloat16(v);
    __nv_bfloat16 lo = __float2bfloat16(v - __bfloat162float(hi));
    g_Wth[n][k] = hi;
    g_Wtl[n][k] = lo;
}

// ---------------- GEMM: g_h0 = dinv ⊙ (x @ W), bf16-split, reg-prefetch ----
#define GBM 128
#define GBK 32
#define SAS 17

__device__ __forceinline__ uint32_t pack_bf16(__nv_bfloat16 a, __nv_bfloat16 b) {
    return (uint32_t)__bfloat16_as_ushort(a) | ((uint32_t)__bfloat16_as_ushort(b) << 16);
}

__device__ __forceinline__ void mma16816(float c[4], const uint32_t a[4],
                                         const uint32_t b[2]) {
    asm volatile(
        "mma.sync.aligned.m16n8k16.row.col.f32.bf16.bf16.f32 "
        "{%0,%1,%2,%3}, {%4,%5,%6,%7}, {%8,%9}, {%0,%1,%2,%3};"
        : "+f"(c[0]), "+f"(c[1]), "+f"(c[2]), "+f"(c[3])
        : "r"(a[0]), "r"(a[1]), "r"(a[2]), "r"(a[3]), "r"(b[0]), "r"(b[1]));
}

__global__ __launch_bounds__(256, 2) void gemm_mma_kernel(const float* __restrict__ x) {
    __shared__ uint32_t sAh[GBM][SAS];
    __shared__ uint32_t sAl[GBM][SAS];
    __shared__ uint32_t sBh[OUT_CH][SAS];
    __shared__ uint32_t sBl[OUT_CH][SAS];

    int tid  = threadIdx.x;
    int wid  = tid >> 5, lane = tid & 31;
    int wm   = wid & 3,  wn   = wid >> 2;
    int grp  = lane >> 2, t4  = lane & 3;
    int m0   = blockIdx.x * GBM;

    float c[2][4][4];
    #pragma unroll
    for (int i = 0; i < 2; i++)
        #pragma unroll
        for (int j = 0; j < 4; j++)
            #pragma unroll
            for (int k = 0; k < 4; k++) c[i][j][k] = 0.0f;

    // register staging for the software pipeline
    float4   xr[4];
    uint32_t wh[4], wl[4];

    // prologue: fetch tile k0=0
    #pragma unroll
    for (int i = 0; i < 4; i++) {
        int idx = tid + i * 256;
        int row = idx >> 3, f4 = idx & 7;
        xr[i] = make_float4(0.f, 0.f, 0.f, 0.f);
        if (m0 + row < N_NODES)
            xr[i] = *(const float4*)(x + (size_t)(m0 + row) * IN_CH + f4 * 4);
        int n = idx >> 4, kp = idx & 15;
        wh[i] = ((const uint32_t*)&g_Wth[n][0])[kp];
        wl[i] = ((const uint32_t*)&g_Wtl[n][0])[kp];
    }

    for (int k0 = 0; k0 < IN_CH; k0 += GBK) {
        // stage: registers -> smem (with bf16 split)
        #pragma unroll
        for (int i = 0; i < 4; i++) {
            int idx = tid + i * 256;
            int row = idx >> 3, f4 = idx & 7;
            float4 v = xr[i];
            __nv_bfloat16 hx = __float2bfloat16(v.x);
            __nv_bfloat16 hy = __float2bfloat16(v.y);
            __nv_bfloat16 hz = __float2bfloat16(v.z);
            __nv_bfloat16 hw = __float2bfloat16(v.w);
            sAh[row][f4 * 2]     = pack_bf16(hx, hy);
            sAh[row][f4 * 2 + 1] = pack_bf16(hz, hw);
            __nv_bfloat16 lx = __float2bfloat16(v.x - __bfloat162float(hx));
            __nv_bfloat16 ly = __float2bfloat16(v.y - __bfloat162float(hy));
            __nv_bfloat16 lz = __float2bfloat16(v.z - __bfloat162float(hz));
            __nv_bfloat16 lw = __float2bfloat16(v.w - __bfloat162float(hw));
            sAl[row][f4 * 2]     = pack_bf16(lx, ly);
            sAl[row][f4 * 2 + 1] = pack_bf16(lz, lw);
            int n = idx >> 4, kp = idx & 15;
            sBh[n][kp] = wh[i];
            sBl[n][kp] = wl[i];
        }
        __syncthreads();

        // prefetch next tile (overlaps with the MMA block below)
        int kn = k0 + GBK;
        if (kn < IN_CH) {
            #pragma unroll
            for (int i = 0; i < 4; i++) {
                int idx = tid + i * 256;
                int row = idx >> 3, f4 = idx & 7;
                xr[i] = make_float4(0.f, 0.f, 0.f, 0.f);
                if (m0 + row < N_NODES)
                    xr[i] = *(const float4*)(x + (size_t)(m0 + row) * IN_CH + kn + f4 * 4);
                int n = idx >> 4, kp = idx & 15;
                wh[i] = ((const uint32_t*)&g_Wth[n][kn])[kp];
                wl[i] = ((const uint32_t*)&g_Wtl[n][kn])[kp];
            }
        }

        #pragma unroll
        for (int kt = 0; kt < 2; kt++) {
            int kp0 = kt * 8;
            uint32_t ah[2][4], al[2][4];
            #pragma unroll
            for (int mt = 0; mt < 2; mt++) {
                int r = wm * 32 + mt * 16 + grp;
                ah[mt][0] = sAh[r][kp0 + t4];
                ah[mt][1] = sAh[r + 8][kp0 + t4];
                ah[mt][2] = sAh[r][kp0 + t4 + 4];
                ah[mt][3] = sAh[r + 8][kp0 + t4 + 4];
                al[mt][0] = sAl[r][kp0 + t4];
                al[mt][1] = sAl[r + 8][kp0 + t4];
                al[mt][2] = sAl[r][kp0 + t4 + 4];
                al[mt][3] = sAl[r + 8][kp0 + t4 + 4];
            }
            uint32_t bh[4][2], bl[4][2];
            #pragma unroll
            for (int nt = 0; nt < 4; nt++) {
                int n = wn * 32 + nt * 8 + grp;
                bh[nt][0] = sBh[n][kp0 + t4];
                bh[nt][1] = sBh[n][kp0 + t4 + 4];
                bl[nt][0] = sBl[n][kp0 + t4];
                bl[nt][1] = sBl[n][kp0 + t4 + 4];
            }
            #pragma unroll
            for (int mt = 0; mt < 2; mt++)
                #pragma unroll
                for (int nt = 0; nt < 4; nt++) {
                    mma16816(c[mt][nt], ah[mt], bh[nt]);
                    mma16816(c[mt][nt], ah[mt], bl[nt]);
                    mma16816(c[mt][nt], al[mt], bh[nt]);
                }
        }
        __syncthreads();
    }

    // epilogue: scale by dinv, store h0s (fp32)
    #pragma unroll
    for (int mt = 0; mt < 2; mt++) {
        int r0 = m0 + wm * 32 + mt * 16 + grp;
        int r1 = r0 + 8;
        float d0 = (r0 < N_NODES) ? g_dinv[r0] : 0.0f;
        float d1 = (r1 < N_NODES) ? g_dinv[r1] : 0.0f;
        #pragma unroll
        for (int nt = 0; nt < 4; nt++) {
            int col = wn * 32 + nt * 8 + t4 * 2;
            if (r0 < N_NODES) {
                float2 v = make_float2(c[mt][nt][0] * d0, c[mt][nt][1] * d0);
                *(float2*)(g_h0 + (size_t)r0 * OUT_CH + col) = v;
            }
            if (r1 < N_NODES) {
                float2 v = make_float2(c[mt][nt][2] * d1, c[mt][nt][3] * d1);
                *(float2*)(g_h0 + (size_t)r1 * OUT_CH + col) = v;
            }
        }
    }
}

// ---------------- gather-based propagation (one warp per node, fp32) --------
// MODE 0: hin=g_h0, hout=g_h1, scale=d^2.  MODE 1: hin=g_h1, hout=outp, scale=d
template <int MODE>
__global__ __launch_bounds__(256) void gather_kernel(float* __restrict__ outp) {
    int node = (int)((blockIdx.x * blockDim.x + threadIdx.x) >> 5);
    if (node >= N_NODES) return;
    int lane = threadIdx.x & 31;

    const float* __restrict__ hin  = (MODE == 0) ? g_h0 : g_h1;
    float*       __restrict__ hout = (MODE == 0) ? g_h1 : outp;

    int start = g_rowptr[node];
    int end   = g_rowptr[node + 1];
    int c4 = (lane & 15) << 2;          // float4 column offset: 0..60

    float4 acc = make_float4(0.f, 0.f, 0.f, 0.f);
    #pragma unroll 4
    for (int e = start + (lane >> 4); e < end; e += 2) {
        int c = g_ecol[e];
        float4 v = *(const float4*)(hin + (size_t)c * OUT_CH + c4);
        acc.x += v.x; acc.y += v.y; acc.z += v.z; acc.w += v.w;
    }
    acc.x += __shfl_xor_sync(0xFFFFFFFFu, acc.x, 16);
    acc.y += __shfl_xor_sync(0xFFFFFFFFu, acc.y, 16);
    acc.z += __shfl_xor_sync(0xFFFFFFFFu, acc.z, 16);
    acc.w += __shfl_xor_sync(0xFFFFFFFFu, acc.w, 16);

    if (lane < 16) {
        float d = g_dinv[node];
        float s = (MODE == 0) ? d * d : d;
        float4 sv = *(const float4*)(hin + (size_t)node * OUT_CH + c4);
        acc.x = s * (acc.x + sv.x);
        acc.y = s * (acc.y + sv.y);
        acc.z = s * (acc.z + sv.z);
        acc.w = s * (acc.w + sv.w);
        *(float4*)(hout + (size_t)node * OUT_CH + c4) = acc;
    }
}

extern "C" void kernel_launch(void* const* d_in, const int* in_sizes, int n_in,
                              void* d_out, int out_size) {
    const void*  edge_index = d_in[0];               // [2, N_EDGES] int32 or int64
    const float* x          = (const float*)d_in[1]; // [N_NODES, 512]
    const float* W          = (const float*)d_in[2]; // [512, 64]
    float*       out        = (float*)d_out;         // [N_NODES, 64]

    zero_detect_kernel<<<(N_NODES + 255) / 256, 256>>>((const int*)edge_index);
    hist_kernel<<<(N_EDGES + 255) / 256, 256>>>(edge_index);

    scanA_kernel<<<SCAN_B, 1024>>>();
    scanB_kernel<<<1, 32>>>();
    scanC_kernel<<<SCAN_B, 1024>>>();
    scatter_kernel<<<(N_EDGES + 255) / 256, 256>>>(edge_index);

    wsplit_kernel<<<(IN_CH * OUT_CH + 255) / 256, 256>>>(W);
    gemm_mma_kernel<<<(N_NODES + GBM - 1) / GBM, 256>>>(x);

    const int blocks = (N_NODES * 32 + 255) / 256;
    gather_kernel<0><<<blocks, 256>>>(nullptr);
    gather_kernel<1><<<blocks, 256>>>(out);
}

// round 9
// speedup vs baseline: 1.5720x; 1.0825x over previous
#include <cuda_runtime.h>
#include <cuda_bf16.h>
#include <cstdint>

#define N_NODES 100000
#define N_EDGES 3200000
#define IN_CH   512
#define OUT_CH  64
#define SCAN_B  98          // ceil(N_NODES / 1024)

// ---- scratch: __device__ globals only ----
__device__ int g_is64;
__device__ __align__(16) int   g_cnt   [N_NODES];
__device__ __align__(16) int   g_rowptr[N_NODES + 1];
__device__ __align__(16) int   g_bsum  [SCAN_B];
__device__ __align__(16) int   g_bbase [SCAN_B];
__device__ __align__(16) float g_dinv  [N_NODES];
__device__ __align__(16) int   g_ecol  [N_EDGES];
__device__ __align__(16) float g_h0    [(size_t)N_NODES * OUT_CH];  // xW, then dinv*(xW)
__device__ __align__(16) float g_h1    [(size_t)N_NODES * OUT_CH];
__device__ __align__(16) __nv_bfloat16 g_Wth[OUT_CH][IN_CH];
__device__ __align__(16) __nv_bfloat16 g_Wtl[OUT_CH][IN_CH];

// ---------------- zero counts + dtype probe (one launch) ----------------
__global__ void zero_detect_kernel(const int* __restrict__ buf) {
    int i = blockIdx.x * blockDim.x + threadIdx.x;
    if (i < N_NODES) g_cnt[i] = 0;
    if (blockIdx.x == 0 && threadIdx.x == 0) {
        int any_odd_nonzero = 0;
        for (int j = 0; j < 2048; j++) {
            if (buf[2 * j + 1] != 0) { any_odd_nonzero = 1; break; }
        }
        g_is64 = any_odd_nonzero ? 0 : 1;
    }
}

__device__ __forceinline__ void load_edge(const void* buf, int e, int& r, int& c) {
    if (g_is64) {
        const long long* p = (const long long*)buf;
        r = (int)p[e];
        c = (int)p[(size_t)N_EDGES + e];
    } else {
        const int* p = (const int*)buf;
        r = p[e];
        c = p[N_EDGES + e];
    }
}

__global__ void hist_kernel(const void* __restrict__ buf) {
    int e = blockIdx.x * blockDim.x + threadIdx.x;
    if (e >= N_EDGES) return;
    int r, c;
    load_edge(buf, e, r, c);
    if ((unsigned)r >= N_NODES || (unsigned)c >= N_NODES) return;
    if (r != c) atomicAdd(&g_cnt[r], 1);
}

// ---------------- 3-phase scan: g_cnt -> g_rowptr (+ dinv in phase C) -------
__global__ __launch_bounds__(1024) void scanA_kernel() {
    __shared__ int wsum[32];
    int b = blockIdx.x, t = threadIdx.x;
    int i = b * 1024 + t;
    int v = (i < N_NODES) ? g_cnt[i] : 0;
    int lane = t & 31, wid = t >> 5;
    int s = v;
    #pragma unroll
    for (int off = 16; off > 0; off >>= 1) s += __shfl_xor_sync(~0u, s, off);
    if (lane == 0) wsum[wid] = s;
    __syncthreads();
    if (wid == 0) {
        int w = wsum[lane];
        #pragma unroll
        for (int off = 16; off > 0; off >>= 1) w += __shfl_xor_sync(~0u, w, off);
        if (lane == 0) g_bsum[b] = w;
    }
}

// warp-parallel scan of the SCAN_B partials
__global__ void scanB_kernel() {
    int lane = threadIdx.x;                 // 32 threads
    int v[4];
    int local = 0;
    #pragma unroll
    for (int j = 0; j < 4; j++) {
        int i = lane * 4 + j;
        v[j] = (i < SCAN_B) ? g_bsum[i] : 0;
        local += v[j];
    }
    int incl = local;
    #pragma unroll
    for (int off = 1; off < 32; off <<= 1) {
        int n = __shfl_up_sync(~0u, incl, off);
        if (lane >= off) incl += n;
    }
    int run = incl - local;
    #pragma unroll
    for (int j = 0; j < 4; j++) {
        int i = lane * 4 + j;
        if (i < SCAN_B) g_bbase[i] = run;
        run += v[j];
    }
    if (lane == 31) g_rowptr[N_NODES] = incl;
}

__global__ __launch_bounds__(1024) void scanC_kernel() {
    __shared__ int wsum[32];
    int b = blockIdx.x, t = threadIdx.x;
    int i = b * 1024 + t;
    int v = (i < N_NODES) ? g_cnt[i] : 0;
    int lane = t & 31, wid = t >> 5;
    int incl = v;
    #pragma unroll
    for (int off = 1; off < 32; off <<= 1) {
        int n = __shfl_up_sync(~0u, incl, off);
        if (lane >= off) incl += n;
    }
    if (lane == 31) wsum[wid] = incl;
    __syncthreads();
    if (wid == 0) {
        int s = wsum[lane];
        #pragma unroll
        for (int off = 1; off < 32; off <<= 1) {
            int n = __shfl_up_sync(~0u, s, off);
            if (lane >= off) s += n;
        }
        wsum[lane] = s;
    }
    __syncthreads();
    if (i < N_NODES) {
        int excl = incl - v + (wid > 0 ? wsum[wid - 1] : 0) + g_bbase[b];
        g_rowptr[i] = excl;
        g_dinv[i]   = rsqrtf((float)v + 1.0f);
    }
}

__global__ void scatter_kernel(const void* __restrict__ buf) {
    int e = blockIdx.x * blockDim.x + threadIdx.x;
    if (e >= N_EDGES) return;
    int r, c;
    load_edge(buf, e, r, c);
    if ((unsigned)r >= N_NODES || (unsigned)c >= N_NODES) return;
    if (r == c) return;
    int left = atomicSub(&g_cnt[r], 1);
    g_ecol[g_rowptr[r] + left - 1] = c;
}

// ---------------- W split/transpose ----------------
__global__ void wsplit_kernel(const float* __restrict__ W) {
    int t = blockIdx.x * blockDim.x + threadIdx.x;
    if (t >= IN_CH * OUT_CH) return;
    int n = t / IN_CH;
    int k = t % IN_CH;
    float v = W[(size_t)k * OUT_CH + n];
    __nv_bfloat16 hi = __float2bfloat16(v);
    __nv_bfloat16 lo = __float2bfloat16(v - __bfloat162float(hi));
    g_Wth[n][k] = hi;
    g_Wtl[n][k] = lo;
}

// ---------------- GEMM: g_h0 = x @ W (raw, no dinv) -------------------------
#define GBM 128
#define GBK 32
#define SAS 17

__device__ __forceinline__ uint32_t pack_bf16(__nv_bfloat16 a, __nv_bfloat16 b) {
    return (uint32_t)__bfloat16_as_ushort(a) | ((uint32_t)__bfloat16_as_ushort(b) << 16);
}

__device__ __forceinline__ void mma16816(float c[4], const uint32_t a[4],
                                         const uint32_t b[2]) {
    asm volatile(
        "mma.sync.aligned.m16n8k16.row.col.f32.bf16.bf16.f32 "
        "{%0,%1,%2,%3}, {%4,%5,%6,%7}, {%8,%9}, {%0,%1,%2,%3};"
        : "+f"(c[0]), "+f"(c[1]), "+f"(c[2]), "+f"(c[3])
        : "r"(a[0]), "r"(a[1]), "r"(a[2]), "r"(a[3]), "r"(b[0]), "r"(b[1]));
}

__global__ __launch_bounds__(256, 2) void gemm_mma_kernel(const float* __restrict__ x) {
    __shared__ uint32_t sAh[GBM][SAS];
    __shared__ uint32_t sAl[GBM][SAS];
    __shared__ uint32_t sBh[OUT_CH][SAS];
    __shared__ uint32_t sBl[OUT_CH][SAS];

    int tid  = threadIdx.x;
    int wid  = tid >> 5, lane = tid & 31;
    int wm   = wid & 3,  wn   = wid >> 2;
    int grp  = lane >> 2, t4  = lane & 3;
    int m0   = blockIdx.x * GBM;

    float c[2][4][4];
    #pragma unroll
    for (int i = 0; i < 2; i++)
        #pragma unroll
        for (int j = 0; j < 4; j++)
            #pragma unroll
            for (int k = 0; k < 4; k++) c[i][j][k] = 0.0f;

    float4   xr[4];
    uint32_t wh[4], wl[4];

    #pragma unroll
    for (int i = 0; i < 4; i++) {
        int idx = tid + i * 256;
        int row = idx >> 3, f4 = idx & 7;
        xr[i] = make_float4(0.f, 0.f, 0.f, 0.f);
        if (m0 + row < N_NODES)
            xr[i] = *(const float4*)(x + (size_t)(m0 + row) * IN_CH + f4 * 4);
        int n = idx >> 4, kp = idx & 15;
        wh[i] = ((const uint32_t*)&g_Wth[n][0])[kp];
        wl[i] = ((const uint32_t*)&g_Wtl[n][0])[kp];
    }

    for (int k0 = 0; k0 < IN_CH; k0 += GBK) {
        #pragma unroll
        for (int i = 0; i < 4; i++) {
            int idx = tid + i * 256;
            int row = idx >> 3, f4 = idx & 7;
            float4 v = xr[i];
            __nv_bfloat16 hx = __float2bfloat16(v.x);
            __nv_bfloat16 hy = __float2bfloat16(v.y);
            __nv_bfloat16 hz = __float2bfloat16(v.z);
            __nv_bfloat16 hw = __float2bfloat16(v.w);
            sAh[row][f4 * 2]     = pack_bf16(hx, hy);
            sAh[row][f4 * 2 + 1] = pack_bf16(hz, hw);
            __nv_bfloat16 lx = __float2bfloat16(v.x - __bfloat162float(hx));
            __nv_bfloat16 ly = __float2bfloat16(v.y - __bfloat162float(hy));
            __nv_bfloat16 lz = __float2bfloat16(v.z - __bfloat162float(hz));
            __nv_bfloat16 lw = __float2bfloat16(v.w - __bfloat162float(hw));
            sAl[row][f4 * 2]     = pack_bf16(lx, ly);
            sAl[row][f4 * 2 + 1] = pack_bf16(lz, lw);
            int n = idx >> 4, kp = idx & 15;
            sBh[n][kp] = wh[i];
            sBl[n][kp] = wl[i];
        }
        __syncthreads();

        int kn = k0 + GBK;
        if (kn < IN_CH) {
            #pragma unroll
            for (int i = 0; i < 4; i++) {
                int idx = tid + i * 256;
                int row = idx >> 3, f4 = idx & 7;
                xr[i] = make_float4(0.f, 0.f, 0.f, 0.f);
                if (m0 + row < N_NODES)
                    xr[i] = *(const float4*)(x + (size_t)(m0 + row) * IN_CH + kn + f4 * 4);
                int n = idx >> 4, kp = idx & 15;
                wh[i] = ((const uint32_t*)&g_Wth[n][kn])[kp];
                wl[i] = ((const uint32_t*)&g_Wtl[n][kn])[kp];
            }
        }

        #pragma unroll
        for (int kt = 0; kt < 2; kt++) {
            int kp0 = kt * 8;
            uint32_t ah[2][4], al[2][4];
            #pragma unroll
            for (int mt = 0; mt < 2; mt++) {
                int r = wm * 32 + mt * 16 + grp;
                ah[mt][0] = sAh[r][kp0 + t4];
                ah[mt][1] = sAh[r + 8][kp0 + t4];
                ah[mt][2] = sAh[r][kp0 + t4 + 4];
                ah[mt][3] = sAh[r + 8][kp0 + t4 + 4];
                al[mt][0] = sAl[r][kp0 + t4];
                al[mt][1] = sAl[r + 8][kp0 + t4];
                al[mt][2] = sAl[r][kp0 + t4 + 4];
                al[mt][3] = sAl[r + 8][kp0 + t4 + 4];
            }
            uint32_t bh[4][2], bl[4][2];
            #pragma unroll
            for (int nt = 0; nt < 4; nt++) {
                int n = wn * 32 + nt * 8 + grp;
                bh[nt][0] = sBh[n][kp0 + t4];
                bh[nt][1] = sBh[n][kp0 + t4 + 4];
                bl[nt][0] = sBl[n][kp0 + t4];
                bl[nt][1] = sBl[n][kp0 + t4 + 4];
            }
            #pragma unroll
            for (int mt = 0; mt < 2; mt++)
                #pragma unroll
                for (int nt = 0; nt < 4; nt++) {
                    mma16816(c[mt][nt], ah[mt], bh[nt]);
                    mma16816(c[mt][nt], ah[mt], bl[nt]);
                    mma16816(c[mt][nt], al[mt], bh[nt]);
                }
        }
        __syncthreads();
    }

    // epilogue: store raw xW (dinv applied later by scale_h0_kernel)
    #pragma unroll
    for (int mt = 0; mt < 2; mt++) {
        int r0 = m0 + wm * 32 + mt * 16 + grp;
        int r1 = r0 + 8;
        #pragma unroll
        for (int nt = 0; nt < 4; nt++) {
            int col = wn * 32 + nt * 8 + t4 * 2;
            if (r0 < N_NODES) {
                float2 v = make_float2(c[mt][nt][0], c[mt][nt][1]);
                *(float2*)(g_h0 + (size_t)r0 * OUT_CH + col) = v;
            }
            if (r1 < N_NODES) {
                float2 v = make_float2(c[mt][nt][2], c[mt][nt][3]);
                *(float2*)(g_h0 + (size_t)r1 * OUT_CH + col) = v;
            }
        }
    }
}

// h0 *= dinv[node]  (join point: needs GEMM + scanC)
__global__ void scale_h0_kernel() {
    int idx = blockIdx.x * blockDim.x + threadIdx.x;   // float4 index
    const int total = N_NODES * OUT_CH / 4;
    if (idx >= total) return;
    int node = idx >> 4;
    float s = g_dinv[node];
    float4 v = *(float4*)(g_h0 + (size_t)idx * 4);
    v.x *= s; v.y *= s; v.z *= s; v.w *= s;
    *(float4*)(g_h0 + (size_t)idx * 4) = v;
}

// ---------------- gather-based propagation (one warp per node, fp32) --------
// MODE 0: hin=g_h0, hout=g_h1, scale=d^2.  MODE 1: hin=g_h1, hout=outp, scale=d
template <int MODE>
__global__ __launch_bounds__(256) void gather_kernel(float* __restrict__ outp) {
    int node = (int)((blockIdx.x * blockDim.x + threadIdx.x) >> 5);
    if (node >= N_NODES) return;
    int lane = threadIdx.x & 31;

    const float* __restrict__ hin  = (MODE == 0) ? g_h0 : g_h1;
    float*       __restrict__ hout = (MODE == 0) ? g_h1 : outp;

    int start = g_rowptr[node];
    int end   = g_rowptr[node + 1];
    int c4 = (lane & 15) << 2;

    float4 acc = make_float4(0.f, 0.f, 0.f, 0.f);
    #pragma unroll 4
    for (int e = start + (lane >> 4); e < end; e += 2) {
        int c = g_ecol[e];
        float4 v = *(const float4*)(hin + (size_t)c * OUT_CH + c4);
        acc.x += v.x; acc.y += v.y; acc.z += v.z; acc.w += v.w;
    }
    acc.x += __shfl_xor_sync(0xFFFFFFFFu, acc.x, 16);
    acc.y += __shfl_xor_sync(0xFFFFFFFFu, acc.y, 16);
    acc.z += __shfl_xor_sync(0xFFFFFFFFu, acc.z, 16);
    acc.w += __shfl_xor_sync(0xFFFFFFFFu, acc.w, 16);

    if (lane < 16) {
        float d = g_dinv[node];
        float s = (MODE == 0) ? d * d : d;
        float4 sv = *(const float4*)(hin + (size_t)node * OUT_CH + c4);
        acc.x = s * (acc.x + sv.x);
        acc.y = s * (acc.y + sv.y);
        acc.z = s * (acc.z + sv.z);
        acc.w = s * (acc.w + sv.w);
        *(float4*)(hout + (size_t)node * OUT_CH + c4) = acc;
    }
}

extern "C" void kernel_launch(void* const* d_in, const int* in_sizes, int n_in,
                              void* d_out, int out_size) {
    const void*  edge_index = d_in[0];               // [2, N_EDGES] int32 or int64
    const float* x          = (const float*)d_in[1]; // [N_NODES, 512]
    const float* W          = (const float*)d_in[2]; // [512, 64]
    float*       out        = (float*)d_out;         // [N_NODES, 64]

    // fork a side stream so the GEMM (tensor-bound) overlaps the CSR build
    // (atomic/DRAM-bound). Event fork/join is the supported capture pattern.
    cudaStream_t s1;
    cudaEvent_t  evRoot, evGemm;
    cudaStreamCreateWithFlags(&s1, cudaStreamNonBlocking);
    cudaEventCreateWithFlags(&evRoot, cudaEventDisableTiming);
    cudaEventCreateWithFlags(&evGemm, cudaEventDisableTiming);

    cudaEventRecord(evRoot, 0);
    cudaStreamWaitEvent(s1, evRoot, 0);

    // s1: weight split + raw GEMM (independent of edges)
    wsplit_kernel<<<(IN_CH * OUT_CH + 255) / 256, 256, 0, s1>>>(W);
    gemm_mma_kernel<<<(N_NODES + GBM - 1) / GBM, 256, 0, s1>>>(x);
    cudaEventRecord(evGemm, s1);

    // s0 (capture stream): CSR build chain
    zero_detect_kernel<<<(N_NODES + 255) / 256, 256>>>((const int*)edge_index);
    hist_kernel<<<(N_EDGES + 255) / 256, 256>>>(edge_index);
    scanA_kernel<<<SCAN_B, 1024>>>();
    scanB_kernel<<<1, 32>>>();
    scanC_kernel<<<SCAN_B, 1024>>>();
    scatter_kernel<<<(N_EDGES + 255) / 256, 256>>>(edge_index);

    // join: scale h0 by dinv (needs GEMM + scanC), then the two hops
    cudaStreamWaitEvent(0, evGemm, 0);
    const int vec_total = N_NODES * OUT_CH / 4;
    scale_h0_kernel<<<(vec_total + 255) / 256, 256>>>();

    const int blocks = (N_NODES * 32 + 255) / 256;
    gather_kernel<0><<<blocks, 256>>>(nullptr);
    gather_kernel<1><<<blocks, 256>>>(out);
}

// round 10
// speedup vs baseline: 1.6573x; 1.0542x over previous
#include <cuda_runtime.h>
#include <cuda_fp16.h>
#include <cuda_bf16.h>
#include <cstdint>

#define N_NODES 100000
#define N_EDGES 3200000
#define IN_CH   512
#define OUT_CH  64
#define SCAN_B  98          // ceil(N_NODES / 1024)

// ---- scratch: __device__ globals only ----
__device__ int g_is64;
__device__ __align__(16) int    g_cnt   [N_NODES];
__device__ __align__(16) int    g_rowptr[N_NODES + 1];
__device__ __align__(16) int    g_bsum  [SCAN_B];
__device__ __align__(16) int    g_bbase [SCAN_B];
__device__ __align__(16) float  g_dinv  [N_NODES];
__device__ __align__(16) int    g_ecol  [N_EDGES];
__device__ __align__(16) float  g_u0    [(size_t)N_NODES * OUT_CH]; // raw xW (fp32)
__device__ __align__(16) __half g_h0    [(size_t)N_NODES * OUT_CH]; // h0s = dinv*(xW), fp16
__device__ __align__(16) __half g_h1    [(size_t)N_NODES * OUT_CH]; // h1s, fp16
__device__ __align__(16) __nv_bfloat16 g_Wth[OUT_CH][IN_CH];
__device__ __align__(16) __nv_bfloat16 g_Wtl[OUT_CH][IN_CH];

// ---------------- zero counts + dtype probe (one launch) ----------------
__global__ void zero_detect_kernel(const int* __restrict__ buf) {
    int i = blockIdx.x * blockDim.x + threadIdx.x;
    if (i < N_NODES) g_cnt[i] = 0;
    if (blockIdx.x == 0 && threadIdx.x == 0) {
        int any_odd_nonzero = 0;
        for (int j = 0; j < 2048; j++) {
            if (buf[2 * j + 1] != 0) { any_odd_nonzero = 1; break; }
        }
        g_is64 = any_odd_nonzero ? 0 : 1;
    }
}

__device__ __forceinline__ void load_edge(const void* buf, int e, int& r, int& c) {
    if (g_is64) {
        const long long* p = (const long long*)buf;
        r = (int)p[e];
        c = (int)p[(size_t)N_EDGES + e];
    } else {
        const int* p = (const int*)buf;
        r = p[e];
        c = p[N_EDGES + e];
    }
}

__global__ void hist_kernel(const void* __restrict__ buf) {
    int e = blockIdx.x * blockDim.x + threadIdx.x;
    if (e >= N_EDGES) return;
    int r, c;
    load_edge(buf, e, r, c);
    if ((unsigned)r >= N_NODES || (unsigned)c >= N_NODES) return;
    if (r != c) atomicAdd(&g_cnt[r], 1);
}

// ---------------- 3-phase scan: g_cnt -> g_rowptr (+ dinv in phase C) -------
__global__ __launch_bounds__(1024) void scanA_kernel() {
    __shared__ int wsum[32];
    int b = blockIdx.x, t = threadIdx.x;
    int i = b * 1024 + t;
    int v = (i < N_NODES) ? g_cnt[i] : 0;
    int lane = t & 31, wid = t >> 5;
    int s = v;
    #pragma unroll
    for (int off = 16; off > 0; off >>= 1) s += __shfl_xor_sync(~0u, s, off);
    if (lane == 0) wsum[wid] = s;
    __syncthreads();
    if (wid == 0) {
        int w = wsum[lane];
        #pragma unroll
        for (int off = 16; off > 0; off >>= 1) w += __shfl_xor_sync(~0u, w, off);
        if (lane == 0) g_bsum[b] = w;
    }
}

__global__ void scanB_kernel() {
    int lane = threadIdx.x;                 // 32 threads
    int v[4];
    int local = 0;
    #pragma unroll
    for (int j = 0; j < 4; j++) {
        int i = lane * 4 + j;
        v[j] = (i < SCAN_B) ? g_bsum[i] : 0;
        local += v[j];
    }
    int incl = local;
    #pragma unroll
    for (int off = 1; off < 32; off <<= 1) {
        int n = __shfl_up_sync(~0u, incl, off);
        if (lane >= off) incl += n;
    }
    int run = incl - local;
    #pragma unroll
    for (int j = 0; j < 4; j++) {
        int i = lane * 4 + j;
        if (i < SCAN_B) g_bbase[i] = run;
        run += v[j];
    }
    if (lane == 31) g_rowptr[N_NODES] = incl;
}

__global__ __launch_bounds__(1024) void scanC_kernel() {
    __shared__ int wsum[32];
    int b = blockIdx.x, t = threadIdx.x;
    int i = b * 1024 + t;
    int v = (i < N_NODES) ? g_cnt[i] : 0;
    int lane = t & 31, wid = t >> 5;
    int incl = v;
    #pragma unroll
    for (int off = 1; off < 32; off <<= 1) {
        int n = __shfl_up_sync(~0u, incl, off);
        if (lane >= off) incl += n;
    }
    if (lane == 31) wsum[wid] = incl;
    __syncthreads();
    if (wid == 0) {
        int s = wsum[lane];
        #pragma unroll
        for (int off = 1; off < 32; off <<= 1) {
            int n = __shfl_up_sync(~0u, s, off);
            if (lane >= off) s += n;
        }
        wsum[lane] = s;
    }
    __syncthreads();
    if (i < N_NODES) {
        int excl = incl - v + (wid > 0 ? wsum[wid - 1] : 0) + g_bbase[b];
        g_rowptr[i] = excl;
        g_dinv[i]   = rsqrtf((float)v + 1.0f);
    }
}

__global__ void scatter_kernel(const void* __restrict__ buf) {
    int e = blockIdx.x * blockDim.x + threadIdx.x;
    if (e >= N_EDGES) return;
    int r, c;
    load_edge(buf, e, r, c);
    if ((unsigned)r >= N_NODES || (unsigned)c >= N_NODES) return;
    if (r == c) return;
    int left = atomicSub(&g_cnt[r], 1);
    g_ecol[g_rowptr[r] + left - 1] = c;
}

// ---------------- W split/transpose ----------------
__global__ void wsplit_kernel(const float* __restrict__ W) {
    int t = blockIdx.x * blockDim.x + threadIdx.x;
    if (t >= IN_CH * OUT_CH) return;
    int n = t / IN_CH;
    int k = t % IN_CH;
    float v = W[(size_t)k * OUT_CH + n];
    __nv_bfloat16 hi = __float2bfloat16(v);
    __nv_bfloat16 lo = __float2bfloat16(v - __bfloat162float(hi));
    g_Wth[n][k] = hi;
    g_Wtl[n][k] = lo;
}

// ---------------- GEMM: g_u0 = x @ W (raw fp32) -----------------------------
#define GBM 128
#define GBK 32
#define SAS 17

__device__ __forceinline__ uint32_t pack_bf16(__nv_bfloat16 a, __nv_bfloat16 b) {
    return (uint32_t)__bfloat16_as_ushort(a) | ((uint32_t)__bfloat16_as_ushort(b) << 16);
}

__device__ __forceinline__ void mma16816(float c[4], const uint32_t a[4],
                                         const uint32_t b[2]) {
    asm volatile(
        "mma.sync.aligned.m16n8k16.row.col.f32.bf16.bf16.f32 "
        "{%0,%1,%2,%3}, {%4,%5,%6,%7}, {%8,%9}, {%0,%1,%2,%3};"
        : "+f"(c[0]), "+f"(c[1]), "+f"(c[2]), "+f"(c[3])
        : "r"(a[0]), "r"(a[1]), "r"(a[2]), "r"(a[3]), "r"(b[0]), "r"(b[1]));
}

__global__ __launch_bounds__(256, 2) void gemm_mma_kernel(const float* __restrict__ x) {
    __shared__ uint32_t sAh[GBM][SAS];
    __shared__ uint32_t sAl[GBM][SAS];
    __shared__ uint32_t sBh[OUT_CH][SAS];
    __shared__ uint32_t sBl[OUT_CH][SAS];

    int tid  = threadIdx.x;
    int wid  = tid >> 5, lane = tid & 31;
    int wm   = wid & 3,  wn   = wid >> 2;
    int grp  = lane >> 2, t4  = lane & 3;
    int m0   = blockIdx.x * GBM;

    float c[2][4][4];
    #pragma unroll
    for (int i = 0; i < 2; i++)
        #pragma unroll
        for (int j = 0; j < 4; j++)
            #pragma unroll
            for (int k = 0; k < 4; k++) c[i][j][k] = 0.0f;

    float4   xr[4];
    uint32_t wh[4], wl[4];

    #pragma unroll
    for (int i = 0; i < 4; i++) {
        int idx = tid + i * 256;
        int row = idx >> 3, f4 = idx & 7;
        xr[i] = make_float4(0.f, 0.f, 0.f, 0.f);
        if (m0 + row < N_NODES)
            xr[i] = *(const float4*)(x + (size_t)(m0 + row) * IN_CH + f4 * 4);
        int n = idx >> 4, kp = idx & 15;
        wh[i] = ((const uint32_t*)&g_Wth[n][0])[kp];
        wl[i] = ((const uint32_t*)&g_Wtl[n][0])[kp];
    }

    for (int k0 = 0; k0 < IN_CH; k0 += GBK) {
        #pragma unroll
        for (int i = 0; i < 4; i++) {
            int idx = tid + i * 256;
            int row = idx >> 3, f4 = idx & 7;
            float4 v = xr[i];
            __nv_bfloat16 hx = __float2bfloat16(v.x);
            __nv_bfloat16 hy = __float2bfloat16(v.y);
            __nv_bfloat16 hz = __float2bfloat16(v.z);
            __nv_bfloat16 hw = __float2bfloat16(v.w);
            sAh[row][f4 * 2]     = pack_bf16(hx, hy);
            sAh[row][f4 * 2 + 1] = pack_bf16(hz, hw);
            __nv_bfloat16 lx = __float2bfloat16(v.x - __bfloat162float(hx));
            __nv_bfloat16 ly = __float2bfloat16(v.y - __bfloat162float(hy));
            __nv_bfloat16 lz = __float2bfloat16(v.z - __bfloat162float(hz));
            __nv_bfloat16 lw = __float2bfloat16(v.w - __bfloat162float(hw));
            sAl[row][f4 * 2]     = pack_bf16(lx, ly);
            sAl[row][f4 * 2 + 1] = pack_bf16(lz, lw);
            int n = idx >> 4, kp = idx & 15;
            sBh[n][kp] = wh[i];
            sBl[n][kp] = wl[i];
        }
        __syncthreads();

        int kn = k0 + GBK;
        if (kn < IN_CH) {
            #pragma unroll
            for (int i = 0; i < 4; i++) {
                int idx = tid + i * 256;
                int row = idx >> 3, f4 = idx & 7;
                xr[i] = make_float4(0.f, 0.f, 0.f, 0.f);
                if (m0 + row < N_NODES)
                    xr[i] = *(const float4*)(x + (size_t)(m0 + row) * IN_CH + kn + f4 * 4);
                int n = idx >> 4, kp = idx & 15;
                wh[i] = ((const uint32_t*)&g_Wth[n][kn])[kp];
                wl[i] = ((const uint32_t*)&g_Wtl[n][kn])[kp];
            }
        }

        #pragma unroll
        for (int kt = 0; kt < 2; kt++) {
            int kp0 = kt * 8;
            uint32_t ah[2][4], al[2][4];
            #pragma unroll
            for (int mt = 0; mt < 2; mt++) {
                int r = wm * 32 + mt * 16 + grp;
                ah[mt][0] = sAh[r][kp0 + t4];
                ah[mt][1] = sAh[r + 8][kp0 + t4];
                ah[mt][2] = sAh[r][kp0 + t4 + 4];
                ah[mt][3] = sAh[r + 8][kp0 + t4 + 4];
                al[mt][0] = sAl[r][kp0 + t4];
                al[mt][1] = sAl[r + 8][kp0 + t4];
                al[mt][2] = sAl[r][kp0 + t4 + 4];
                al[mt][3] = sAl[r + 8][kp0 + t4 + 4];
            }
            uint32_t bh[4][2], bl[4][2];
            #pragma unroll
            for (int nt = 0; nt < 4; nt++) {
                int n = wn * 32 + nt * 8 + grp;
                bh[nt][0] = sBh[n][kp0 + t4];
                bh[nt][1] = sBh[n][kp0 + t4 + 4];
                bl[nt][0] = sBl[n][kp0 + t4];
                bl[nt][1] = sBl[n][kp0 + t4 + 4];
            }
            #pragma unroll
            for (int mt = 0; mt < 2; mt++)
                #pragma unroll
                for (int nt = 0; nt < 4; nt++) {
                    mma16816(c[mt][nt], ah[mt], bh[nt]);
                    mma16816(c[mt][nt], ah[mt], bl[nt]);
                    mma16816(c[mt][nt], al[mt], bh[nt]);
                }
        }
        __syncthreads();
    }

    #pragma unroll
    for (int mt = 0; mt < 2; mt++) {
        int r0 = m0 + wm * 32 + mt * 16 + grp;
        int r1 = r0 + 8;
        #pragma unroll
        for (int nt = 0; nt < 4; nt++) {
            int col = wn * 32 + nt * 8 + t4 * 2;
            if (r0 < N_NODES) {
                float2 v = make_float2(c[mt][nt][0], c[mt][nt][1]);
                *(float2*)(g_u0 + (size_t)r0 * OUT_CH + col) = v;
            }
            if (r1 < N_NODES) {
                float2 v = make_float2(c[mt][nt][2], c[mt][nt][3]);
                *(float2*)(g_u0 + (size_t)r1 * OUT_CH + col) = v;
            }
        }
    }
}

// h0 = fp16( dinv[node] * u0 )   (join point: needs GEMM + scanC)
__global__ void scale_h0_kernel() {
    int idx = blockIdx.x * blockDim.x + threadIdx.x;   // 4-elem chunk index
    const int total = N_NODES * OUT_CH / 4;
    if (idx >= total) return;
    int node = idx >> 4;
    float s = g_dinv[node];
    float4 v = *(const float4*)(g_u0 + (size_t)idx * 4);
    __half2 h0 = __floats2half2_rn(v.x * s, v.y * s);
    __half2 h1 = __floats2half2_rn(v.z * s, v.w * s);
    uint2 u;
    u.x = *(uint32_t*)&h0;
    u.y = *(uint32_t*)&h1;
    *(uint2*)(g_h0 + (size_t)idx * 4) = u;
}

// ---------------- gather propagation: fp16 rows, R7-proven loop shape -------
// 16 lanes per edge, 8 B (4 halves) per lane; 2 edges per warp-iteration.
// MODE 0: hin=g_h0, hout=g_h1 (fp16), scale=d^2
// MODE 1: hin=g_h1, hout=outp (fp32), scale=d
template <int MODE>
__global__ __launch_bounds__(256) void gather_kernel(float* __restrict__ outp) {
    int node = (int)((blockIdx.x * blockDim.x + threadIdx.x) >> 5);
    if (node >= N_NODES) return;
    int lane = threadIdx.x & 31;

    const __half* __restrict__ hin = (MODE == 0) ? g_h0 : g_h1;

    int start = g_rowptr[node];
    int end   = g_rowptr[node + 1];
    int ch = (lane & 15) << 2;          // half-element offset: 0,4,...,60

    float4 acc = make_float4(0.f, 0.f, 0.f, 0.f);
    #pragma unroll 4
    for (int e = start + (lane >> 4); e < end; e += 2) {
        int c = g_ecol[e];
        uint2 u = *(const uint2*)(hin + (size_t)c * OUT_CH + ch);
        float2 f0 = __half22float2(*(__half2*)&u.x);
        float2 f1 = __half22float2(*(__half2*)&u.y);
        acc.x += f0.x; acc.y += f0.y; acc.z += f1.x; acc.w += f1.y;
    }
    acc.x += __shfl_xor_sync(0xFFFFFFFFu, acc.x, 16);
    acc.y += __shfl_xor_sync(0xFFFFFFFFu, acc.y, 16);
    acc.z += __shfl_xor_sync(0xFFFFFFFFu, acc.z, 16);
    acc.w += __shfl_xor_sync(0xFFFFFFFFu, acc.w, 16);

    if (lane < 16) {
        float d = g_dinv[node];
        float s = (MODE == 0) ? d * d : d;
        uint2 su = *(const uint2*)(hin + (size_t)node * OUT_CH + ch);
        float2 s0 = __half22float2(*(__half2*)&su.x);
        float2 s1 = __half22float2(*(__half2*)&su.y);
        acc.x = s * (acc.x + s0.x);
        acc.y = s * (acc.y + s0.y);
        acc.z = s * (acc.z + s1.x);
        acc.w = s * (acc.w + s1.y);

        if (MODE == 0) {
            __half2 o0 = __floats2half2_rn(acc.x, acc.y);
            __half2 o1 = __floats2half2_rn(acc.z, acc.w);
            uint2 u;
            u.x = *(uint32_t*)&o0;
            u.y = *(uint32_t*)&o1;
            *(uint2*)(g_h1 + (size_t)node * OUT_CH + ch) = u;
        } else {
            *(float4*)(outp + (size_t)node * OUT_CH + ch) = acc;
        }
    }
}

extern "C" void kernel_launch(void* const* d_in, const int* in_sizes, int n_in,
                              void* d_out, int out_size) {
    const void*  edge_index = d_in[0];               // [2, N_EDGES] int32 or int64
    const float* x          = (const float*)d_in[1]; // [N_NODES, 512]
    const float* W          = (const float*)d_in[2]; // [512, 64]
    float*       out        = (float*)d_out;         // [N_NODES, 64]

    // fork a side stream: GEMM (tensor-bound) overlaps the CSR build
    cudaStream_t s1;
    cudaEvent_t  evRoot, evGemm;
    cudaStreamCreateWithFlags(&s1, cudaStreamNonBlocking);
    cudaEventCreateWithFlags(&evRoot, cudaEventDisableTiming);
    cudaEventCreateWithFlags(&evGemm, cudaEventDisableTiming);

    cudaEventRecord(evRoot, 0);
    cudaStreamWaitEvent(s1, evRoot, 0);

    wsplit_kernel<<<(IN_CH * OUT_CH + 255) / 256, 256, 0, s1>>>(W);
    gemm_mma_kernel<<<(N_NODES + GBM - 1) / GBM, 256, 0, s1>>>(x);
    cudaEventRecord(evGemm, s1);

    zero_detect_kernel<<<(N_NODES + 255) / 256, 256>>>((const int*)edge_index);
    hist_kernel<<<(N_EDGES + 255) / 256, 256>>>(edge_index);
    scanA_kernel<<<SCAN_B, 1024>>>();
    scanB_kernel<<<1, 32>>>();
    scanC_kernel<<<SCAN_B, 1024>>>();
    scatter_kernel<<<(N_EDGES + 255) / 256, 256>>>(edge_index);

    cudaStreamWaitEvent(0, evGemm, 0);
    const int vec_total = N_NODES * OUT_CH / 4;
    scale_h0_kernel<<<(vec_total + 255) / 256, 256>>>();

    const int blocks = (N_NODES * 32 + 255) / 256;
    gather_kernel<0><<<blocks, 256>>>(nullptr);
    gather_kernel<1><<<blocks, 256>>>(out);
}

// round 11
// speedup vs baseline: 1.6877x; 1.0184x over previous
#include <cuda_runtime.h>
#include <cuda_fp16.h>
#include <cuda_bf16.h>
#include <cstdint>

#define N_NODES 100000
#define N_EDGES 3200000
#define IN_CH   512
#define OUT_CH  64
#define SCAN_B  98          // ceil(N_NODES / 1024)

// ---- scratch: __device__ globals only ----
__device__ int g_is64;
__device__ __align__(16) int    g_cnt   [N_NODES];
__device__ __align__(16) int    g_rowptr[N_NODES + 1];
__device__ __align__(16) int    g_bsum  [SCAN_B];
__device__ __align__(16) int    g_bbase [SCAN_B];
__device__ __align__(16) float  g_dinv  [N_NODES];
__device__ __align__(16) int    g_ecol  [N_EDGES];
__device__ __align__(16) float  g_u0    [(size_t)N_NODES * OUT_CH]; // raw xW (fp32)
__device__ __align__(16) __half g_h0    [(size_t)N_NODES * OUT_CH]; // h0s = dinv*(xW)
__device__ __align__(16) __half g_h1    [(size_t)N_NODES * OUT_CH]; // h1s
__device__ __align__(16) __nv_bfloat16 g_Wth[OUT_CH][IN_CH];
__device__ __align__(16) __nv_bfloat16 g_Wtl[OUT_CH][IN_CH];

// ---------------- zero counts + dtype probe (one launch) ----------------
__global__ void zero_detect_kernel(const int* __restrict__ buf) {
    int i = blockIdx.x * blockDim.x + threadIdx.x;
    if (i < N_NODES) g_cnt[i] = 0;
    if (blockIdx.x == 0 && threadIdx.x == 0) {
        int any_odd_nonzero = 0;
        for (int j = 0; j < 2048; j++) {
            if (buf[2 * j + 1] != 0) { any_odd_nonzero = 1; break; }
        }
        g_is64 = any_odd_nonzero ? 0 : 1;
    }
}

__device__ __forceinline__ void load_edge(const void* buf, int e, int& r, int& c) {
    if (g_is64) {
        const long long* p = (const long long*)buf;
        r = (int)p[e];
        c = (int)p[(size_t)N_EDGES + e];
    } else {
        const int* p = (const int*)buf;
        r = p[e];
        c = p[N_EDGES + e];
    }
}

__global__ void hist_kernel(const void* __restrict__ buf) {
    int e = blockIdx.x * blockDim.x + threadIdx.x;
    if (e >= N_EDGES) return;
    int r, c;
    load_edge(buf, e, r, c);
    if ((unsigned)r >= N_NODES || (unsigned)c >= N_NODES) return;
    if (r != c) atomicAdd(&g_cnt[r], 1);
}

// ---------------- 3-phase scan: g_cnt -> g_rowptr (+ dinv in phase C) -------
__global__ __launch_bounds__(1024) void scanA_kernel() {
    __shared__ int wsum[32];
    int b = blockIdx.x, t = threadIdx.x;
    int i = b * 1024 + t;
    int v = (i < N_NODES) ? g_cnt[i] : 0;
    int lane = t & 31, wid = t >> 5;
    int s = v;
    #pragma unroll
    for (int off = 16; off > 0; off >>= 1) s += __shfl_xor_sync(~0u, s, off);
    if (lane == 0) wsum[wid] = s;
    __syncthreads();
    if (wid == 0) {
        int w = wsum[lane];
        #pragma unroll
        for (int off = 16; off > 0; off >>= 1) w += __shfl_xor_sync(~0u, w, off);
        if (lane == 0) g_bsum[b] = w;
    }
}

__global__ void scanB_kernel() {
    int lane = threadIdx.x;                 // 32 threads
    int v[4];
    int local = 0;
    #pragma unroll
    for (int j = 0; j < 4; j++) {
        int i = lane * 4 + j;
        v[j] = (i < SCAN_B) ? g_bsum[i] : 0;
        local += v[j];
    }
    int incl = local;
    #pragma unroll
    for (int off = 1; off < 32; off <<= 1) {
        int n = __shfl_up_sync(~0u, incl, off);
        if (lane >= off) incl += n;
    }
    int run = incl - local;
    #pragma unroll
    for (int j = 0; j < 4; j++) {
        int i = lane * 4 + j;
        if (i < SCAN_B) g_bbase[i] = run;
        run += v[j];
    }
    if (lane == 31) g_rowptr[N_NODES] = incl;
}

__global__ __launch_bounds__(1024) void scanC_kernel() {
    __shared__ int wsum[32];
    int b = blockIdx.x, t = threadIdx.x;
    int i = b * 1024 + t;
    int v = (i < N_NODES) ? g_cnt[i] : 0;
    int lane = t & 31, wid = t >> 5;
    int incl = v;
    #pragma unroll
    for (int off = 1; off < 32; off <<= 1) {
        int n = __shfl_up_sync(~0u, incl, off);
        if (lane >= off) incl += n;
    }
    if (lane == 31) wsum[wid] = incl;
    __syncthreads();
    if (wid == 0) {
        int s = wsum[lane];
        #pragma unroll
        for (int off = 1; off < 32; off <<= 1) {
            int n = __shfl_up_sync(~0u, s, off);
            if (lane >= off) s += n;
        }
        wsum[lane] = s;
    }
    __syncthreads();
    if (i < N_NODES) {
        int excl = incl - v + (wid > 0 ? wsum[wid - 1] : 0) + g_bbase[b];
        g_rowptr[i] = excl;
        g_dinv[i]   = rsqrtf((float)v + 1.0f);
    }
}

__global__ void scatter_kernel(const void* __restrict__ buf) {
    int e = blockIdx.x * blockDim.x + threadIdx.x;
    if (e >= N_EDGES) return;
    int r, c;
    load_edge(buf, e, r, c);
    if ((unsigned)r >= N_NODES || (unsigned)c >= N_NODES) return;
    if (r == c) return;
    int left = atomicSub(&g_cnt[r], 1);
    g_ecol[g_rowptr[r] + left - 1] = c;
}

// ---------------- W split/transpose ----------------
__global__ void wsplit_kernel(const float* __restrict__ W) {
    int t = blockIdx.x * blockDim.x + threadIdx.x;
    if (t >= IN_CH * OUT_CH) return;
    int n = t / IN_CH;
    int k = t % IN_CH;
    float v = W[(size_t)k * OUT_CH + n];
    __nv_bfloat16 hi = __float2bfloat16(v);
    __nv_bfloat16 lo = __float2bfloat16(v - __bfloat162float(hi));
    g_Wth[n][k] = hi;
    g_Wtl[n][k] = lo;
}

// ---------------- GEMM: g_u0 = x @ W (raw fp32) -----------------------------
#define GBM 128
#define GBK 32
#define SAS 17

__device__ __forceinline__ uint32_t pack_bf16(__nv_bfloat16 a, __nv_bfloat16 b) {
    return (uint32_t)__bfloat16_as_ushort(a) | ((uint32_t)__bfloat16_as_ushort(b) << 16);
}

__device__ __forceinline__ void mma16816(float c[4], const uint32_t a[4],
                                         const uint32_t b[2]) {
    asm volatile(
        "mma.sync.aligned.m16n8k16.row.col.f32.bf16.bf16.f32 "
        "{%0,%1,%2,%3}, {%4,%5,%6,%7}, {%8,%9}, {%0,%1,%2,%3};"
        : "+f"(c[0]), "+f"(c[1]), "+f"(c[2]), "+f"(c[3])
        : "r"(a[0]), "r"(a[1]), "r"(a[2]), "r"(a[3]), "r"(b[0]), "r"(b[1]));
}

__global__ __launch_bounds__(256, 2) void gemm_mma_kernel(const float* __restrict__ x) {
    __shared__ uint32_t sAh[GBM][SAS];
    __shared__ uint32_t sAl[GBM][SAS];
    __shared__ uint32_t sBh[OUT_CH][SAS];
    __shared__ uint32_t sBl[OUT_CH][SAS];

    int tid  = threadIdx.x;
    int wid  = tid >> 5, lane = tid & 31;
    int wm   = wid & 3,  wn   = wid >> 2;
    int grp  = lane >> 2, t4  = lane & 3;
    int m0   = blockIdx.x * GBM;

    float c[2][4][4];
    #pragma unroll
    for (int i = 0; i < 2; i++)
        #pragma unroll
        for (int j = 0; j < 4; j++)
            #pragma unroll
            for (int k = 0; k < 4; k++) c[i][j][k] = 0.0f;

    float4   xr[4];
    uint32_t wh[4], wl[4];

    #pragma unroll
    for (int i = 0; i < 4; i++) {
        int idx = tid + i * 256;
        int row = idx >> 3, f4 = idx & 7;
        xr[i] = make_float4(0.f, 0.f, 0.f, 0.f);
        if (m0 + row < N_NODES)
            xr[i] = *(const float4*)(x + (size_t)(m0 + row) * IN_CH + f4 * 4);
        int n = idx >> 4, kp = idx & 15;
        wh[i] = ((const uint32_t*)&g_Wth[n][0])[kp];
        wl[i] = ((const uint32_t*)&g_Wtl[n][0])[kp];
    }

    for (int k0 = 0; k0 < IN_CH; k0 += GBK) {
        #pragma unroll
        for (int i = 0; i < 4; i++) {
            int idx = tid + i * 256;
            int row = idx >> 3, f4 = idx & 7;
            float4 v = xr[i];
            __nv_bfloat16 hx = __float2bfloat16(v.x);
            __nv_bfloat16 hy = __float2bfloat16(v.y);
            __nv_bfloat16 hz = __float2bfloat16(v.z);
            __nv_bfloat16 hw = __float2bfloat16(v.w);
            sAh[row][f4 * 2]     = pack_bf16(hx, hy);
            sAh[row][f4 * 2 + 1] = pack_bf16(hz, hw);
            __nv_bfloat16 lx = __float2bfloat16(v.x - __bfloat162float(hx));
            __nv_bfloat16 ly = __float2bfloat16(v.y - __bfloat162float(hy));
            __nv_bfloat16 lz = __float2bfloat16(v.z - __bfloat162float(hz));
            __nv_bfloat16 lw = __float2bfloat16(v.w - __bfloat162float(hw));
            sAl[row][f4 * 2]     = pack_bf16(lx, ly);
            sAl[row][f4 * 2 + 1] = pack_bf16(lz, lw);
            int n = idx >> 4, kp = idx & 15;
            sBh[n][kp] = wh[i];
            sBl[n][kp] = wl[i];
        }
        __syncthreads();

        int kn = k0 + GBK;
        if (kn < IN_CH) {
            #pragma unroll
            for (int i = 0; i < 4; i++) {
                int idx = tid + i * 256;
                int row = idx >> 3, f4 = idx & 7;
                xr[i] = make_float4(0.f, 0.f, 0.f, 0.f);
                if (m0 + row < N_NODES)
                    xr[i] = *(const float4*)(x + (size_t)(m0 + row) * IN_CH + kn + f4 * 4);
                int n = idx >> 4, kp = idx & 15;
                wh[i] = ((const uint32_t*)&g_Wth[n][kn])[kp];
                wl[i] = ((const uint32_t*)&g_Wtl[n][kn])[kp];
            }
        }

        #pragma unroll
        for (int kt = 0; kt < 2; kt++) {
            int kp0 = kt * 8;
            uint32_t ah[2][4], al[2][4];
            #pragma unroll
            for (int mt = 0; mt < 2; mt++) {
                int r = wm * 32 + mt * 16 + grp;
                ah[mt][0] = sAh[r][kp0 + t4];
                ah[mt][1] = sAh[r + 8][kp0 + t4];
                ah[mt][2] = sAh[r][kp0 + t4 + 4];
                ah[mt][3] = sAh[r + 8][kp0 + t4 + 4];
                al[mt][0] = sAl[r][kp0 + t4];
                al[mt][1] = sAl[r + 8][kp0 + t4];
                al[mt][2] = sAl[r][kp0 + t4 + 4];
                al[mt][3] = sAl[r + 8][kp0 + t4 + 4];
            }
            uint32_t bh[4][2], bl[4][2];
            #pragma unroll
            for (int nt = 0; nt < 4; nt++) {
                int n = wn * 32 + nt * 8 + grp;
                bh[nt][0] = sBh[n][kp0 + t4];
                bh[nt][1] = sBh[n][kp0 + t4 + 4];
                bl[nt][0] = sBl[n][kp0 + t4];
                bl[nt][1] = sBl[n][kp0 + t4 + 4];
            }
            #pragma unroll
            for (int mt = 0; mt < 2; mt++)
                #pragma unroll
                for (int nt = 0; nt < 4; nt++) {
                    mma16816(c[mt][nt], ah[mt], bh[nt]);
                    mma16816(c[mt][nt], ah[mt], bl[nt]);
                    mma16816(c[mt][nt], al[mt], bh[nt]);
                }
        }
        __syncthreads();
    }

    #pragma unroll
    for (int mt = 0; mt < 2; mt++) {
        int r0 = m0 + wm * 32 + mt * 16 + grp;
        int r1 = r0 + 8;
        #pragma unroll
        for (int nt = 0; nt < 4; nt++) {
            int col = wn * 32 + nt * 8 + t4 * 2;
            if (r0 < N_NODES) {
                float2 v = make_float2(c[mt][nt][0], c[mt][nt][1]);
                *(float2*)(g_u0 + (size_t)r0 * OUT_CH + col) = v;
            }
            if (r1 < N_NODES) {
                float2 v = make_float2(c[mt][nt][2], c[mt][nt][3]);
                *(float2*)(g_u0 + (size_t)r1 * OUT_CH + col) = v;
            }
        }
    }
}

// h0 = fp16( dinv[node] * u0 )   (needs GEMM + scanC; runs ∥ scatter)
__global__ void scale_h0_kernel() {
    int idx = blockIdx.x * blockDim.x + threadIdx.x;   // 4-elem chunk index
    const int total = N_NODES * OUT_CH / 4;
    if (idx >= total) return;
    int node = idx >> 4;
    float s = g_dinv[node];
    float4 v = *(const float4*)(g_u0 + (size_t)idx * 4);
    __half2 h0 = __floats2half2_rn(v.x * s, v.y * s);
    __half2 h1 = __floats2half2_rn(v.z * s, v.w * s);
    uint2 u;
    u.x = *(uint32_t*)&h0;
    u.y = *(uint32_t*)&h1;
    *(uint2*)(g_h0 + (size_t)idx * 4) = u;
}

// ---------------- gather: fp16 rows, software-pipelined ecol prefetch -------
// 16 lanes/edge, 2 edges per logical iter; groups of 4 iters (8 edges) with
// the NEXT group's ecol indices loaded while the current group's rows are
// in flight — breaks the dependent ecol->row latency chain.
// MODE 0: hin=g_h0, hout=g_h1 (fp16), scale=d^2
// MODE 1: hin=g_h1, hout=outp (fp32), scale=d
template <int MODE>
__global__ __launch_bounds__(256) void gather_kernel(float* __restrict__ outp) {
    int node = (int)((blockIdx.x * blockDim.x + threadIdx.x) >> 5);
    if (node >= N_NODES) return;
    int lane = threadIdx.x & 31;

    const __half* __restrict__ hin = (MODE == 0) ? g_h0 : g_h1;

    int start = g_rowptr[node];
    int end   = g_rowptr[node + 1];
    int ch   = (lane & 15) << 2;        // half-element offset: 0,4,...,60
    int half = lane >> 4;               // 0 or 1

    float4 acc = make_float4(0.f, 0.f, 0.f, 0.f);

    int e0 = start + half;
    int c[4];
    #pragma unroll
    for (int j = 0; j < 4; j++) {
        int e = e0 + j * 2;
        c[j] = (e < end) ? g_ecol[e] : -1;
    }
    for (int base = e0; base < end; base += 8) {
        int cn[4];
        #pragma unroll
        for (int j = 0; j < 4; j++) {
            int e = base + 8 + j * 2;
            cn[j] = (e < end) ? g_ecol[e] : -1;
        }
        #pragma unroll
        for (int j = 0; j < 4; j++) {
            if (c[j] >= 0) {
                uint2 u = *(const uint2*)(hin + (size_t)c[j] * OUT_CH + ch);
                float2 f0 = __half22float2(*(__half2*)&u.x);
                float2 f1 = __half22float2(*(__half2*)&u.y);
                acc.x += f0.x; acc.y += f0.y; acc.z += f1.x; acc.w += f1.y;
            }
        }
        #pragma unroll
        for (int j = 0; j < 4; j++) c[j] = cn[j];
    }

    acc.x += __shfl_xor_sync(0xFFFFFFFFu, acc.x, 16);
    acc.y += __shfl_xor_sync(0xFFFFFFFFu, acc.y, 16);
    acc.z += __shfl_xor_sync(0xFFFFFFFFu, acc.z, 16);
    acc.w += __shfl_xor_sync(0xFFFFFFFFu, acc.w, 16);

    if (lane < 16) {
        float d = g_dinv[node];
        float s = (MODE == 0) ? d * d : d;
        uint2 su = *(const uint2*)(hin + (size_t)node * OUT_CH + ch);
        float2 s0 = __half22float2(*(__half2*)&su.x);
        float2 s1 = __half22float2(*(__half2*)&su.y);
        acc.x = s * (acc.x + s0.x);
        acc.y = s * (acc.y + s0.y);
        acc.z = s * (acc.z + s1.x);
        acc.w = s * (acc.w + s1.y);

        if (MODE == 0) {
            __half2 o0 = __floats2half2_rn(acc.x, acc.y);
            __half2 o1 = __floats2half2_rn(acc.z, acc.w);
            uint2 u;
            u.x = *(uint32_t*)&o0;
            u.y = *(uint32_t*)&o1;
            *(uint2*)(g_h1 + (size_t)node * OUT_CH + ch) = u;
        } else {
            *(float4*)(outp + (size_t)node * OUT_CH + ch) = acc;
        }
    }
}

extern "C" void kernel_launch(void* const* d_in, const int* in_sizes, int n_in,
                              void* d_out, int out_size) {
    const void*  edge_index = d_in[0];               // [2, N_EDGES] int32 or int64
    const float* x          = (const float*)d_in[1]; // [N_NODES, 512]
    const float* W          = (const float*)d_in[2]; // [512, 64]
    float*       out        = (float*)d_out;         // [N_NODES, 64]

    cudaStream_t s1;
    cudaEvent_t  evRoot, evScan, evScale;
    cudaStreamCreateWithFlags(&s1, cudaStreamNonBlocking);
    cudaEventCreateWithFlags(&evRoot,  cudaEventDisableTiming);
    cudaEventCreateWithFlags(&evScan,  cudaEventDisableTiming);
    cudaEventCreateWithFlags(&evScale, cudaEventDisableTiming);

    cudaEventRecord(evRoot, 0);
    cudaStreamWaitEvent(s1, evRoot, 0);

    // s1: weight split + raw GEMM (needs only x, W)
    wsplit_kernel<<<(IN_CH * OUT_CH + 255) / 256, 256, 0, s1>>>(W);
    gemm_mma_kernel<<<(N_NODES + GBM - 1) / GBM, 256, 0, s1>>>(x);

    // s0: CSR build chain
    zero_detect_kernel<<<(N_NODES + 255) / 256, 256>>>((const int*)edge_index);
    hist_kernel<<<(N_EDGES + 255) / 256, 256>>>(edge_index);
    scanA_kernel<<<SCAN_B, 1024>>>();
    scanB_kernel<<<1, 32>>>();
    scanC_kernel<<<SCAN_B, 1024>>>();
    cudaEventRecord(evScan, 0);

    // s1: scale_h0 (needs GEMM [program order on s1] + scanC [event]) —
    // runs concurrently with scatter on s0.
    cudaStreamWaitEvent(s1, evScan, 0);
    const int vec_total = N_NODES * OUT_CH / 4;
    scale_h0_kernel<<<(vec_total + 255) / 256, 256, 0, s1>>>();
    cudaEventRecord(evScale, s1);

    // s0: scatter ∥ scale_h0, then join and run the two hops
    scatter_kernel<<<(N_EDGES + 255) / 256, 256>>>(edge_index);
    cudaStreamWaitEvent(0, evScale, 0);

    const int blocks = (N_NODES * 32 + 255) / 256;
    gather_kernel<0><<<blocks, 256>>>(nullptr);
    gather_kernel<1><<<blocks, 256>>>(out);
}

// round 13
// speedup vs baseline: 1.7234x; 1.0212x over previous
#include <cuda_runtime.h>
#include <cuda_fp16.h>
#include <cuda_bf16.h>
#include <cstdint>

#define N_NODES 100000
#define N_EDGES 3200000
#define IN_CH   512
#define OUT_CH  64
#define SCAN_B  98          // ceil(N_NODES / 1024)

// ---- scratch: __device__ globals only ----
__device__ int g_is64;
__device__ __align__(16) int    g_cnt   [N_NODES];
__device__ __align__(16) int    g_rowptr[N_NODES + 1];
__device__ __align__(16) int    g_bsum  [SCAN_B];
__device__ __align__(16) int    g_bbase [SCAN_B];
__device__ __align__(16) float  g_dinv  [N_NODES];
__device__ __align__(16) int    g_ecol  [N_EDGES];
__device__ __align__(16) float  g_u0    [(size_t)N_NODES * OUT_CH]; // raw xW (fp32)
__device__ __align__(16) __half g_h0    [(size_t)N_NODES * OUT_CH]; // h0s = dinv*(xW)
__device__ __align__(16) __half g_h1    [(size_t)N_NODES * OUT_CH]; // h1s
__device__ __align__(16) __nv_bfloat16 g_Wth[OUT_CH][IN_CH];
__device__ __align__(16) __nv_bfloat16 g_Wtl[OUT_CH][IN_CH];

// ---------------- zero counts + dtype probe (one launch) ----------------
__global__ void zero_detect_kernel(const int* __restrict__ buf) {
    int i = blockIdx.x * blockDim.x + threadIdx.x;
    if (i < N_NODES) g_cnt[i] = 0;
    if (blockIdx.x == 0 && threadIdx.x == 0) {
        int any_odd_nonzero = 0;
        for (int j = 0; j < 2048; j++) {
            if (buf[2 * j + 1] != 0) { any_odd_nonzero = 1; break; }
        }
        g_is64 = any_odd_nonzero ? 0 : 1;
    }
}

// load TWO consecutive edges (2e, 2e+1) with vector index loads
__device__ __forceinline__ void load_edge2(const void* buf, int e2,
                                           int& r0, int& c0, int& r1, int& c1) {
    if (g_is64) {
        const longlong2* pr = (const longlong2*)((const long long*)buf) + e2;
        const longlong2* pc = (const longlong2*)((const long long*)buf + N_EDGES) + e2;
        longlong2 rr = *pr;
        longlong2 cc = *pc;
        r0 = (int)rr.x; r1 = (int)rr.y;
        c0 = (int)cc.x; c1 = (int)cc.y;
    } else {
        const int2* pr = (const int2*)((const int*)buf) + e2;
        const int2* pc = (const int2*)((const int*)buf + N_EDGES) + e2;
        int2 rr = *pr;
        int2 cc = *pc;
        r0 = rr.x; r1 = rr.y;
        c0 = cc.x; c1 = cc.y;
    }
}

__global__ void hist_kernel(const void* __restrict__ buf) {
    int e2 = blockIdx.x * blockDim.x + threadIdx.x;   // edge-pair index
    if (e2 >= N_EDGES / 2) return;
    int r0, c0, r1, c1;
    load_edge2(buf, e2, r0, c0, r1, c1);
    if ((unsigned)r0 < N_NODES && (unsigned)c0 < N_NODES && r0 != c0)
        atomicAdd(&g_cnt[r0], 1);
    if ((unsigned)r1 < N_NODES && (unsigned)c1 < N_NODES && r1 != c1)
        atomicAdd(&g_cnt[r1], 1);
}

// ---------------- 3-phase scan: g_cnt -> g_rowptr (+ dinv in phase C) -------
__global__ __launch_bounds__(1024) void scanA_kernel() {
    __shared__ int wsum[32];
    int b = blockIdx.x, t = threadIdx.x;
    int i = b * 1024 + t;
    int v = (i < N_NODES) ? g_cnt[i] : 0;
    int lane = t & 31, wid = t >> 5;
    int s = v;
    #pragma unroll
    for (int off = 16; off > 0; off >>= 1) s += __shfl_xor_sync(~0u, s, off);
    if (lane == 0) wsum[wid] = s;
    __syncthreads();
    if (wid == 0) {
        int w = wsum[lane];
        #pragma unroll
        for (int off = 16; off > 0; off >>= 1) w += __shfl_xor_sync(~0u, w, off);
        if (lane == 0) g_bsum[b] = w;
    }
}

__global__ void scanB_kernel() {
    int lane = threadIdx.x;                 // 32 threads
    int v[4];
    int local = 0;
    #pragma unroll
    for (int j = 0; j < 4; j++) {
        int i = lane * 4 + j;
        v[j] = (i < SCAN_B) ? g_bsum[i] : 0;
        local += v[j];
    }
    int incl = local;
    #pragma unroll
    for (int off = 1; off < 32; off <<= 1) {
        int n = __shfl_up_sync(~0u, incl, off);
        if (lane >= off) incl += n;
    }
    int run = incl - local;
    #pragma unroll
    for (int j = 0; j < 4; j++) {
        int i = lane * 4 + j;
        if (i < SCAN_B) g_bbase[i] = run;
        run += v[j];
    }
    if (lane == 31) g_rowptr[N_NODES] = incl;
}

__global__ __launch_bounds__(1024) void scanC_kernel() {
    __shared__ int wsum[32];
    int b = blockIdx.x, t = threadIdx.x;
    int i = b * 1024 + t;
    int v = (i < N_NODES) ? g_cnt[i] : 0;
    int lane = t & 31, wid = t >> 5;
    int incl = v;
    #pragma unroll
    for (int off = 1; off < 32; off <<= 1) {
        int n = __shfl_up_sync(~0u, incl, off);
        if (lane >= off) incl += n;
    }
    if (lane == 31) wsum[wid] = incl;
    __syncthreads();
    if (wid == 0) {
        int s = wsum[lane];
        #pragma unroll
        for (int off = 1; off < 32; off <<= 1) {
            int n = __shfl_up_sync(~0u, s, off);
            if (lane >= off) s += n;
        }
        wsum[lane] = s;
    }
    __syncthreads();
    if (i < N_NODES) {
        int excl = incl - v + (wid > 0 ? wsum[wid - 1] : 0) + g_bbase[b];
        g_rowptr[i] = excl;
        g_dinv[i]   = rsqrtf((float)v + 1.0f);
    }
}

__global__ void scatter_kernel(const void* __restrict__ buf) {
    int e2 = blockIdx.x * blockDim.x + threadIdx.x;
    if (e2 >= N_EDGES / 2) return;
    int r0, c0, r1, c1;
    load_edge2(buf, e2, r0, c0, r1, c1);
    if ((unsigned)r0 < N_NODES && (unsigned)c0 < N_NODES && r0 != c0) {
        int left = atomicSub(&g_cnt[r0], 1);
        g_ecol[g_rowptr[r0] + left - 1] = c0;
    }
    if ((unsigned)r1 < N_NODES && (unsigned)c1 < N_NODES && r1 != c1) {
        int left = atomicSub(&g_cnt[r1], 1);
        g_ecol[g_rowptr[r1] + left - 1] = c1;
    }
}

// ---------------- W split/transpose ----------------
__global__ void wsplit_kernel(const float* __restrict__ W) {
    int t = blockIdx.x * blockDim.x + threadIdx.x;
    if (t >= IN_CH * OUT_CH) return;
    int n = t / IN_CH;
    int k = t % IN_CH;
    float v = W[(size_t)k * OUT_CH + n];
    __nv_bfloat16 hi = __float2bfloat16(v);
    __nv_bfloat16 lo = __float2bfloat16(v - __bfloat162float(hi));
    g_Wth[n][k] = hi;
    g_Wtl[n][k] = lo;
}

// ---------------- GEMM: g_u0 = x @ W (raw fp32) -----------------------------
#define GBM 128
#define GBK 32
#define SAS 17

__device__ __forceinline__ uint32_t pack_bf16(__nv_bfloat16 a, __nv_bfloat16 b) {
    return (uint32_t)__bfloat16_as_ushort(a) | ((uint32_t)__bfloat16_as_ushort(b) << 16);
}

__device__ __forceinline__ void mma16816(float c[4], const uint32_t a[4],
                                         const uint32_t b[2]) {
    asm volatile(
        "mma.sync.aligned.m16n8k16.row.col.f32.bf16.bf16.f32 "
        "{%0,%1,%2,%3}, {%4,%5,%6,%7}, {%8,%9}, {%0,%1,%2,%3};"
        : "+f"(c[0]), "+f"(c[1]), "+f"(c[2]), "+f"(c[3])
        : "r"(a[0]), "r"(a[1]), "r"(a[2]), "r"(a[3]), "r"(b[0]), "r"(b[1]));
}

__global__ __launch_bounds__(256, 2) void gemm_mma_kernel(const float* __restrict__ x) {
    __shared__ uint32_t sAh[GBM][SAS];
    __shared__ uint32_t sAl[GBM][SAS];
    __shared__ uint32_t sBh[OUT_CH][SAS];
    __shared__ uint32_t sBl[OUT_CH][SAS];

    int tid  = threadIdx.x;
    int wid  = tid >> 5, lane = tid & 31;
    int wm   = wid & 3,  wn   = wid >> 2;
    int grp  = lane >> 2, t4  = lane & 3;
    int m0   = blockIdx.x * GBM;

    float c[2][4][4];
    #pragma unroll
    for (int i = 0; i < 2; i++)
        #pragma unroll
        for (int j = 0; j < 4; j++)
            #pragma unroll
            for (int k = 0; k < 4; k++) c[i][j][k] = 0.0f;

    float4   xr[4];
    uint32_t wh[4], wl[4];

    #pragma unroll
    for (int i = 0; i < 4; i++) {
        int idx = tid + i * 256;
        int row = idx >> 3, f4 = idx & 7;
        xr[i] = make_float4(0.f, 0.f, 0.f, 0.f);
        if (m0 + row < N_NODES)
            xr[i] = *(const float4*)(x + (size_t)(m0 + row) * IN_CH + f4 * 4);
        int n = idx >> 4, kp = idx & 15;
        wh[i] = ((const uint32_t*)&g_Wth[n][0])[kp];
        wl[i] = ((const uint32_t*)&g_Wtl[n][0])[kp];
    }

    for (int k0 = 0; k0 < IN_CH; k0 += GBK) {
        #pragma unroll
        for (int i = 0; i < 4; i++) {
            int idx = tid + i * 256;
            int row = idx >> 3, f4 = idx & 7;
            float4 v = xr[i];
            __nv_bfloat16 hx = __float2bfloat16(v.x);
            __nv_bfloat16 hy = __float2bfloat16(v.y);
            __nv_bfloat16 hz = __float2bfloat16(v.z);
            __nv_bfloat16 hw = __float2bfloat16(v.w);
            sAh[row][f4 * 2]     = pack_bf16(hx, hy);
            sAh[row][f4 * 2 + 1] = pack_bf16(hz, hw);
            __nv_bfloat16 lx = __float2bfloat16(v.x - __bfloat162float(hx));
            __nv_bfloat16 ly = __float2bfloat16(v.y - __bfloat162float(hy));
            __nv_bfloat16 lz = __float2bfloat16(v.z - __bfloat162float(hz));
            __nv_bfloat16 lw = __float2bfloat16(v.w - __bfloat162float(hw));
            sAl[row][f4 * 2]     = pack_bf16(lx, ly);
            sAl[row][f4 * 2 + 1] = pack_bf16(lz, lw);
            int n = idx >> 4, kp = idx & 15;
            sBh[n][kp] = wh[i];
            sBl[n][kp] = wl[i];
        }
        __syncthreads();

        int kn = k0 + GBK;
        if (kn < IN_CH) {
            #pragma unroll
            for (int i = 0; i < 4; i++) {
                int idx = tid + i * 256;
                int row = idx >> 3, f4 = idx & 7;
                xr[i] = make_float4(0.f, 0.f, 0.f, 0.f);
                if (m0 + row < N_NODES)
                    xr[i] = *(const float4*)(x + (size_t)(m0 + row) * IN_CH + kn + f4 * 4);
                int n = idx >> 4, kp = idx & 15;
                wh[i] = ((const uint32_t*)&g_Wth[n][kn])[kp];
                wl[i] = ((const uint32_t*)&g_Wtl[n][kn])[kp];
            }
        }

        #pragma unroll
        for (int kt = 0; kt < 2; kt++) {
            int kp0 = kt * 8;
            uint32_t ah[2][4], al[2][4];
            #pragma unroll
            for (int mt = 0; mt < 2; mt++) {
                int r = wm * 32 + mt * 16 + grp;
                ah[mt][0] = sAh[r][kp0 + t4];
                ah[mt][1] = sAh[r + 8][kp0 + t4];
                ah[mt][2] = sAh[r][kp0 + t4 + 4];
                ah[mt][3] = sAh[r + 8][kp0 + t4 + 4];
                al[mt][0] = sAl[r][kp0 + t4];
                al[mt][1] = sAl[r + 8][kp0 + t4];
                al[mt][2] = sAl[r][kp0 + t4 + 4];
                al[mt][3] = sAl[r + 8][kp0 + t4 + 4];
            }
            uint32_t bh[4][2], bl[4][2];
            #pragma unroll
            for (int nt = 0; nt < 4; nt++) {
                int n = wn * 32 + nt * 8 + grp;
                bh[nt][0] = sBh[n][kp0 + t4];
                bh[nt][1] = sBh[n][kp0 + t4 + 4];
                bl[nt][0] = sBl[n][kp0 + t4];
                bl[nt][1] = sBl[n][kp0 + t4 + 4];
            }
            #pragma unroll
            for (int mt = 0; mt < 2; mt++)
                #pragma unroll
                for (int nt = 0; nt < 4; nt++) {
                    mma16816(c[mt][nt], ah[mt], bh[nt]);
                    mma16816(c[mt][nt], ah[mt], bl[nt]);
                    mma16816(c[mt][nt], al[mt], bh[nt]);
                }
        }
        __syncthreads();
    }

    #pragma unroll
    for (int mt = 0; mt < 2; mt++) {
        int r0 = m0 + wm * 32 + mt * 16 + grp;
        int r1 = r0 + 8;
        #pragma unroll
        for (int nt = 0; nt < 4; nt++) {
            int col = wn * 32 + nt * 8 + t4 * 2;
            if (r0 < N_NODES) {
                float2 v = make_float2(c[mt][nt][0], c[mt][nt][1]);
                *(float2*)(g_u0 + (size_t)r0 * OUT_CH + col) = v;
            }
            if (r1 < N_NODES) {
                float2 v = make_float2(c[mt][nt][2], c[mt][nt][3]);
                *(float2*)(g_u0 + (size_t)r1 * OUT_CH + col) = v;
            }
        }
    }
}

// h0 = fp16( dinv[node] * u0 )   (needs GEMM + scanC; runs ∥ scatter)
__global__ void scale_h0_kernel() {
    int idx = blockIdx.x * blockDim.x + threadIdx.x;   // 4-elem chunk index
    const int total = N_NODES * OUT_CH / 4;
    if (idx >= total) return;
    int node = idx >> 4;
    float s = g_dinv[node];
    float4 v = *(const float4*)(g_u0 + (size_t)idx * 4);
    __half2 h0 = __floats2half2_rn(v.x * s, v.y * s);
    __half2 h1 = __floats2half2_rn(v.z * s, v.w * s);
    uint2 u;
    u.x = *(uint32_t*)&h0;
    u.y = *(uint32_t*)&h1;
    *(uint2*)(g_h0 + (size_t)idx * 4) = u;
}

// ---------------- gather: fp16 rows, 8 lanes/edge (4 edges/warp-instr),
// software-pipelined ecol prefetch (8 edges in flight per warp) ------------
// MODE 0: hin=g_h0, hout=g_h1 (fp16), scale=d^2
// MODE 1: hin=g_h1, hout=outp (fp32), scale=d
template <int MODE>
__global__ __launch_bounds__(256) void gather_kernel(float* __restrict__ outp) {
    int node = (int)((blockIdx.x * blockDim.x + threadIdx.x) >> 5);
    if (node >= N_NODES) return;
    int lane = threadIdx.x & 31;

    const __half* __restrict__ hin = (MODE == 0) ? g_h0 : g_h1;

    int start = g_rowptr[node];
    int end   = g_rowptr[node + 1];
    int sub  = lane & 7;                // 8-lane group position
    int ch   = sub << 3;                // half offset: 0,8,...,56 (uint4 = 8 halves)
    int eoff = lane >> 3;               // 0..3: edge slot within warp

    float acc[8];
    #pragma unroll
    for (int i = 0; i < 8; i++) acc[i] = 0.0f;

    int e0 = start + eoff;
    int c[2];
    #pragma unroll
    for (int j = 0; j < 2; j++) {
        int e = e0 + j * 4;
        c[j] = (e < end) ? g_ecol[e] : -1;
    }
    for (int base = e0; base < end; base += 8) {
        int cn[2];
        #pragma unroll
        for (int j = 0; j < 2; j++) {
            int e = base + 8 + j * 4;
            cn[j] = (e < end) ? g_ecol[e] : -1;
        }
        #pragma unroll
        for (int j = 0; j < 2; j++) {
            if (c[j] >= 0) {
                uint4 u = *(const uint4*)(hin + (size_t)c[j] * OUT_CH + ch);
                float2 f;
                f = __half22float2(*(__half2*)&u.x); acc[0] += f.x; acc[1] += f.y;
                f = __half22float2(*(__half2*)&u.y); acc[2] += f.x; acc[3] += f.y;
                f = __half22float2(*(__half2*)&u.z); acc[4] += f.x; acc[5] += f.y;
                f = __half22float2(*(__half2*)&u.w); acc[6] += f.x; acc[7] += f.y;
            }
            c[j] = cn[j];
        }
    }

    // combine the 4 edge-slots (xor 8, xor 16)
    #pragma unroll
    for (int i = 0; i < 8; i++) {
        acc[i] += __shfl_xor_sync(0xFFFFFFFFu, acc[i], 8);
        acc[i] += __shfl_xor_sync(0xFFFFFFFFu, acc[i], 16);
    }

    if (lane < 8) {
        float d = g_dinv[node];
        float s = (MODE == 0) ? d * d : d;
        uint4 su = *(const uint4*)(hin + (size_t)node * OUT_CH + ch);
        float2 f;
        f = __half22float2(*(__half2*)&su.x); acc[0] += f.x; acc[1] += f.y;
        f = __half22float2(*(__half2*)&su.y); acc[2] += f.x; acc[3] += f.y;
        f = __half22float2(*(__half2*)&su.z); acc[4] += f.x; acc[5] += f.y;
        f = __half22float2(*(__half2*)&su.w); acc[6] += f.x; acc[7] += f.y;
        #pragma unroll
        for (int i = 0; i < 8; i++) acc[i] *= s;

        if (MODE == 0) {
            __half2 o[4];
            #pragma unroll
            for (int j = 0; j < 4; j++)
                o[j] = __floats2half2_rn(acc[2 * j], acc[2 * j + 1]);
            *(uint4*)(g_h1 + (size_t)node * OUT_CH + ch) = *(uint4*)o;
        } else {
            float* dst = outp + (size_t)node * OUT_CH + ch;
            *(float4*)(dst)     = make_float4(acc[0], acc[1], acc[2], acc[3]);
            *(float4*)(dst + 4) = make_float4(acc[4], acc[5], acc[6], acc[7]);
        }
    }
}

extern "C" void kernel_launch(void* const* d_in, const int* in_sizes, int n_in,
                              void* d_out, int out_size) {
    const void*  edge_index = d_in[0];               // [2, N_EDGES] int32 or int64
    const float* x          = (const float*)d_in[1]; // [N_NODES, 512]
    const float* W          = (const float*)d_in[2]; // [512, 64]
    float*       out        = (float*)d_out;         // [N_NODES, 64]

    cudaStream_t s1;
    cudaEvent_t  evRoot, evScan, evScale;
    cudaStreamCreateWithFlags(&s1, cudaStreamNonBlocking);
    cudaEventCreateWithFlags(&evRoot,  cudaEventDisableTiming);
    cudaEventCreateWithFlags(&evScan,  cudaEventDisableTiming);
    cudaEventCreateWithFlags(&evScale, cudaEventDisableTiming);

    cudaEventRecord(evRoot, 0);
    cudaStreamWaitEvent(s1, evRoot, 0);

    // s1: weight split + raw GEMM (needs only x, W)
    wsplit_kernel<<<(IN_CH * OUT_CH + 255) / 256, 256, 0, s1>>>(W);
    gemm_mma_kernel<<<(N_NODES + GBM - 1) / GBM, 256, 0, s1>>>(x);

    // s0: CSR build chain (2 edges per thread)
    zero_detect_kernel<<<(N_NODES + 255) / 256, 256>>>((const int*)edge_index);
    hist_kernel<<<(N_EDGES / 2 + 255) / 256, 256>>>(edge_index);
    scanA_kernel<<<SCAN_B, 1024>>>();
    scanB_kernel<<<1, 32>>>();
    scanC_kernel<<<SCAN_B, 1024>>>();
    cudaEventRecord(evScan, 0);

    // s1: scale_h0 (GEMM done on s1; scanC via event) — overlaps scatter
    cudaStreamWaitEvent(s1, evScan, 0);
    const int vec_total = N_NODES * OUT_CH / 4;
    scale_h0_kernel<<<(vec_total + 255) / 256, 256, 0, s1>>>();
    cudaEventRecord(evScale, s1);

    // s0: scatter ∥ scale_h0, then join and run the two hops
    scatter_kernel<<<(N_EDGES / 2 + 255) / 256, 256>>>(edge_index);
    cudaStreamWaitEvent(0, evScale, 0);

    const int blocks = (N_NODES * 32 + 255) / 256;
    gather_kernel<0><<<blocks, 256>>>(nullptr);
    gather_kernel<1><<<blocks, 256>>>(out);
}